// round 12
// baseline (speedup 1.0000x reference)
#include <cuda_runtime.h>
#include <cstdint>

namespace {
constexpr int B = 4, S = 2048, D = 512, H = 8, DK = 64;
}

// Scratch (allocation-free rule: __device__ globals)
__device__ float g_Q[(size_t)B * S * D];
__device__ float g_K[(size_t)B * S * D];
__device__ float g_V[(size_t)B * S * D];
__device__ float g_C[(size_t)B * S * D];
__device__ float g_att[(size_t)B * H * S * S];
__device__ float g_rowM[(size_t)B * H * S];
__device__ float g_rowInv[(size_t)B * H * S];

// ============================================================================
// bf16 split, MMA, ldmatrix, cp.async helpers (portable PTX, compute_103-safe)
// ============================================================================
__device__ __forceinline__ void split_bf16x2(float x0, float x1, uint32_t& hi, uint32_t& lo) {
    asm("cvt.rn.bf16x2.f32 %0, %1, %2;" : "=r"(hi) : "f"(x1), "f"(x0));
    const float h0 = __uint_as_float(hi << 16);
    const float h1 = __uint_as_float(hi & 0xFFFF0000u);
    asm("cvt.rn.bf16x2.f32 %0, %1, %2;" : "=r"(lo) : "f"(x1 - h1), "f"(x0 - h0));
}
__device__ __forceinline__ void mma_bf16(float c[4], const uint32_t a[4], const uint32_t b[2]) {
    asm volatile(
        "mma.sync.aligned.m16n8k16.row.col.f32.bf16.bf16.f32 "
        "{%0,%1,%2,%3}, {%4,%5,%6,%7}, {%8,%9}, {%0,%1,%2,%3};"
        : "+f"(c[0]), "+f"(c[1]), "+f"(c[2]), "+f"(c[3])
        : "r"(a[0]), "r"(a[1]), "r"(a[2]), "r"(a[3]), "r"(b[0]), "r"(b[1]));
}
__device__ __forceinline__ void ldmx4(uint32_t r[4], uint32_t addr) {
    asm volatile("ldmatrix.sync.aligned.m8n8.x4.shared.b16 {%0,%1,%2,%3}, [%4];"
                 : "=r"(r[0]), "=r"(r[1]), "=r"(r[2]), "=r"(r[3]) : "r"(addr));
}
__device__ __forceinline__ void ldmx2(uint32_t r[2], uint32_t addr) {
    asm volatile("ldmatrix.sync.aligned.m8n8.x2.shared.b16 {%0,%1}, [%2];"
                 : "=r"(r[0]), "=r"(r[1]) : "r"(addr));
}
__device__ __forceinline__ uint32_t smaddr(const void* p) {
    return (uint32_t)__cvta_generic_to_shared(p);
}
__device__ __forceinline__ void cp_async16(uint32_t sa, const void* g) {
    asm volatile("cp.async.ca.shared.global [%0], [%1], 16;" :: "r"(sa), "l"(g) : "memory");
}
#define CP_COMMIT() asm volatile("cp.async.commit_group;" ::: "memory")
#define CP_WAIT0()  asm volatile("cp.async.wait_group 0;" ::: "memory")

namespace {
constexpr int KPS = 36;   // bf16x2-pair stride (padded; conflict-free)
}

// ============================================================================
// Projection GEMM (bf16 3-term): Y[M,512] = X @ W^T + bias  (unchanged)
// ============================================================================
namespace {
constexpr int GM_XHI = 0;
constexpr int GM_XLO = 128 * KPS;
constexpr int GM_WHI = 2 * 128 * KPS;
constexpr int GM_WLO = 3 * 128 * KPS;
constexpr int SMEM_GEMM = 4 * 128 * KPS * 4;     // 73,728 bytes
}

__global__ void __launch_bounds__(256, 2) gemm_mma(
    const float* __restrict__ X, const float* __restrict__ W,
    const float* __restrict__ bias, float* __restrict__ Y)
{
    extern __shared__ uint32_t smu[];
    uint32_t* Xhi = smu + GM_XHI;
    uint32_t* Xlo = smu + GM_XLO;
    uint32_t* Whi = smu + GM_WHI;
    uint32_t* Wlo = smu + GM_WLO;

    const int t = threadIdx.x, lane = t & 31, wid = t >> 5;
    const int g = lane >> 2, tig = lane & 3;
    const int wm = wid & 1, wn = wid >> 1;
    const int m0 = blockIdx.y * 128, n0 = blockIdx.x * 128;

    const int am = lane >> 3, arm = lane & 7;
    const int bmat = (lane >> 3) & 1, brm = lane & 7;
    uint32_t aHi[4], aLo[4], bHi[4], bLo[4];
#pragma unroll
    for (int i = 0; i < 4; i++) {
        const int row = wm * 64 + i * 16 + (am & 1) * 8 + arm;
        const uint32_t off = (uint32_t)(row * KPS + (am >> 1) * 4) * 4u;
        aHi[i] = smaddr(Xhi) + off;
        aLo[i] = smaddr(Xlo) + off;
    }
#pragma unroll
    for (int j = 0; j < 4; j++) {
        const int row = wn * 32 + j * 8 + brm;
        const uint32_t off = (uint32_t)(row * KPS + bmat * 4) * 4u;
        bHi[j] = smaddr(Whi) + off;
        bLo[j] = smaddr(Wlo) + off;
    }

    float acc[4][4][4] = {};

    for (int kc = 0; kc < 512; kc += 64) {
#pragma unroll
        for (int i = t; i < 2048; i += 256) {
            const int row = i >> 4, c4 = (i & 15) * 4, p = c4 >> 1;
            float4 xv = *reinterpret_cast<const float4*>(&X[(size_t)(m0 + row) * 512 + kc + c4]);
            float4 wv = *reinterpret_cast<const float4*>(&W[(size_t)(n0 + row) * 512 + kc + c4]);
            uint2 h, l;
            split_bf16x2(xv.x, xv.y, h.x, l.x);
            split_bf16x2(xv.z, xv.w, h.y, l.y);
            *reinterpret_cast<uint2*>(&Xhi[row * KPS + p]) = h;
            *reinterpret_cast<uint2*>(&Xlo[row * KPS + p]) = l;
            split_bf16x2(wv.x, wv.y, h.x, l.x);
            split_bf16x2(wv.z, wv.w, h.y, l.y);
            *reinterpret_cast<uint2*>(&Whi[row * KPS + p]) = h;
            *reinterpret_cast<uint2*>(&Wlo[row * KPS + p]) = l;
        }
        __syncthreads();

#pragma unroll
        for (int ks = 0; ks < 4; ks++) {
            const uint32_t ko = ks * 32u;
            uint32_t ahi[4][4], alo[4][4];
#pragma unroll
            for (int i = 0; i < 4; i++) {
                ldmx4(ahi[i], aHi[i] + ko);
                ldmx4(alo[i], aLo[i] + ko);
            }
#pragma unroll
            for (int j = 0; j < 4; j++) {
                uint32_t bhi[2], blo[2];
                ldmx2(bhi, bHi[j] + ko);
                ldmx2(blo, bLo[j] + ko);
#pragma unroll
                for (int i = 0; i < 4; i++) {
                    mma_bf16(acc[i][j], ahi[i], bhi);
                    mma_bf16(acc[i][j], alo[i], bhi);
                    mma_bf16(acc[i][j], ahi[i], blo);
                }
            }
        }
        __syncthreads();
    }

#pragma unroll
    for (int i = 0; i < 4; i++) {
        const int row0 = m0 + wm * 64 + i * 16 + g;
#pragma unroll
        for (int j = 0; j < 4; j++) {
            const int col = n0 + wn * 32 + j * 8 + 2 * tig;
            const float b0 = __ldg(bias + col), b1 = __ldg(bias + col + 1);
            float2 o;
            o.x = acc[i][j][0] + b0; o.y = acc[i][j][1] + b1;
            *reinterpret_cast<float2*>(&Y[(size_t)row0 * 512 + col]) = o;
            o.x = acc[i][j][2] + b0; o.y = acc[i][j][3] + b1;
            *reinterpret_cast<float2*>(&Y[(size_t)(row0 + 8) * 512 + col]) = o;
        }
    }
}

// ============================================================================
// stats_mma (cp.async pipelined): online (max, sumexp) -> rowM, rowInv
// ============================================================================
namespace {
constexpr int ST_QHI = 0;
constexpr int ST_QLO = 128 * KPS;
constexpr int ST_KHI = 2 * 128 * KPS;
constexpr int ST_KLO = ST_KHI + 64 * KPS;
constexpr int ST_RED = ST_KLO + 64 * KPS;           // 512 floats
constexpr int ST_STG = ST_RED + 512;                // 4096 floats (64x64 raw K)
constexpr int SMEM_STATS = (ST_STG + 4096) * 4;     // 73,728 bytes
}

__global__ void __launch_bounds__(256, 2) stats_mma(
    const float* __restrict__ Q, const float* __restrict__ K,
    const int* __restrict__ mask, const float* __restrict__ is_org,
    const float* __restrict__ Worg, const float* __restrict__ borg,
    float* __restrict__ rowM, float* __restrict__ rowInv)
{
    extern __shared__ uint32_t smu[];
    uint32_t* Qhi = smu + ST_QHI;
    uint32_t* Qlo = smu + ST_QLO;
    uint32_t* Khi = smu + ST_KHI;
    uint32_t* Klo = smu + ST_KLO;
    float* redM = reinterpret_cast<float*>(smu + ST_RED);
    float* redS = redM + 256;
    float* stK  = reinterpret_cast<float*>(smu + ST_STG);
    const uint32_t stKa = smaddr(stK);

    const int t = threadIdx.x, lane = t & 31, wid = t >> 5;
    const int g = lane >> 2, tig = lane & 3;
    const int wm = wid & 3, wn = wid >> 2;
    const int bh = blockIdx.y, b = bh >> 3, h = bh & 7;
    const int q0 = blockIdx.x * 128;

    const float* Qg = Q + ((size_t)(b * S + q0)) * D + h * DK;
    const float* Kg = K + ((size_t)(b * S)) * D + h * DK;

    // Issue cp.async for tile 0 ASAP
#pragma unroll
    for (int i = t; i < 1024; i += 256) {
        const int row = i >> 4, c4 = (i & 15) * 4;
        cp_async16(stKa + (uint32_t)(row * 64 + c4) * 4u,
                   Kg + (size_t)row * D + c4);
    }
    CP_COMMIT();

    // Q tile split
#pragma unroll
    for (int i = t; i < 2048; i += 256) {
        const int row = i >> 4, c4 = (i & 15) * 4, p = c4 >> 1;
        float4 qv = *reinterpret_cast<const float4*>(Qg + (size_t)row * D + c4);
        uint2 h2, l2;
        split_bf16x2(qv.x, qv.y, h2.x, l2.x);
        split_bf16x2(qv.z, qv.w, h2.y, l2.y);
        *reinterpret_cast<uint2*>(&Qhi[row * KPS + p]) = h2;
        *reinterpret_cast<uint2*>(&Qlo[row * KPS + p]) = l2;
    }

    const int am = lane >> 3, arm = lane & 7;
    const int bmat = (lane >> 3) & 1, brm = lane & 7;
    uint32_t aHi[2], aLo[2], bHi[4], bLo[4];
#pragma unroll
    for (int i = 0; i < 2; i++) {
        const int row = wm * 32 + i * 16 + (am & 1) * 8 + arm;
        const uint32_t off = (uint32_t)(row * KPS + (am >> 1) * 4) * 4u;
        aHi[i] = smaddr(Qhi) + off;
        aLo[i] = smaddr(Qlo) + off;
    }
#pragma unroll
    for (int j = 0; j < 4; j++) {
        const int row = wn * 32 + j * 8 + brm;
        const uint32_t off = (uint32_t)(row * KPS + bmat * 4) * 4u;
        bHi[j] = smaddr(Khi) + off;
        bLo[j] = smaddr(Klo) + off;
    }

    const float worg = __ldg(Worg + h), bog = __ldg(borg + h);
    float og[2][2];
#pragma unroll
    for (int i = 0; i < 2; i++)
#pragma unroll
        for (int hh = 0; hh < 2; hh++)
            og[i][hh] = __ldg(is_org + b * S + q0 + wm * 32 + i * 16 + g + hh * 8) * worg + bog;

    float rm[2][2], rs[2][2];
#pragma unroll
    for (int i = 0; i < 2; i++)
#pragma unroll
        for (int hh = 0; hh < 2; hh++) { rm[i][hh] = -1e30f; rs[i][hh] = 0.0f; }

    for (int kt = 0; kt < 32; kt++) {
        CP_WAIT0();
        __syncthreads();                 // stage ready; prior MMA readers done

        // Split stage -> Khi/Klo
#pragma unroll
        for (int i = t; i < 1024; i += 256) {
            const int row = i >> 4, c4 = (i & 15) * 4, p = c4 >> 1;
            float4 kv = *reinterpret_cast<const float4*>(stK + row * 64 + c4);
            uint2 h2, l2;
            split_bf16x2(kv.x, kv.y, h2.x, l2.x);
            split_bf16x2(kv.z, kv.w, h2.y, l2.y);
            *reinterpret_cast<uint2*>(&Khi[row * KPS + p]) = h2;
            *reinterpret_cast<uint2*>(&Klo[row * KPS + p]) = l2;
        }
        __syncthreads();

        // Prefetch next tile under the MMA
        if (kt < 31) {
#pragma unroll
            for (int i = t; i < 1024; i += 256) {
                const int row = i >> 4, c4 = (i & 15) * 4;
                cp_async16(stKa + (uint32_t)(row * 64 + c4) * 4u,
                           Kg + (size_t)((kt + 1) * 64 + row) * D + c4);
            }
            CP_COMMIT();
        }

        float acc[2][4][4] = {};
#pragma unroll
        for (int ks = 0; ks < 4; ks++) {
            const uint32_t ko = ks * 32u;
            uint32_t ahi[2][4], alo[2][4];
#pragma unroll
            for (int i = 0; i < 2; i++) { ldmx4(ahi[i], aHi[i] + ko); ldmx4(alo[i], aLo[i] + ko); }
#pragma unroll
            for (int j = 0; j < 4; j++) {
                uint32_t bhi[2], blo[2];
                ldmx2(bhi, bHi[j] + ko);
                ldmx2(blo, bLo[j] + ko);
#pragma unroll
                for (int i = 0; i < 2; i++) {
                    mma_bf16(acc[i][j], ahi[i], bhi);
                    mma_bf16(acc[i][j], alo[i], bhi);
                    mma_bf16(acc[i][j], ahi[i], blo);
                }
            }
        }

        int2 mj[4];
#pragma unroll
        for (int j = 0; j < 4; j++)
            mj[j] = *reinterpret_cast<const int2*>(mask + b * S + kt * 64 + wn * 32 + j * 8 + 2 * tig);

#pragma unroll
        for (int i = 0; i < 2; i++) {
#pragma unroll
            for (int j = 0; j < 4; j++) {
                float v;
                v = acc[i][j][0] * 0.125f + og[i][0]; acc[i][j][0] = mj[j].x ? v : -1e9f;
                v = acc[i][j][1] * 0.125f + og[i][0]; acc[i][j][1] = mj[j].y ? v : -1e9f;
                v = acc[i][j][2] * 0.125f + og[i][1]; acc[i][j][2] = mj[j].x ? v : -1e9f;
                v = acc[i][j][3] * 0.125f + og[i][1]; acc[i][j][3] = mj[j].y ? v : -1e9f;
            }
        }

#pragma unroll
        for (int i = 0; i < 2; i++) {
#pragma unroll
            for (int hh = 0; hh < 2; hh++) {
                float mt = -1e30f;
#pragma unroll
                for (int j = 0; j < 4; j++)
                    mt = fmaxf(mt, fmaxf(acc[i][j][hh * 2], acc[i][j][hh * 2 + 1]));
                mt = fmaxf(mt, __shfl_xor_sync(0xffffffffu, mt, 1));
                mt = fmaxf(mt, __shfl_xor_sync(0xffffffffu, mt, 2));
                const float mnew = fmaxf(rm[i][hh], mt);
                float st = 0.0f;
#pragma unroll
                for (int j = 0; j < 4; j++)
                    st += __expf(acc[i][j][hh * 2] - mnew) + __expf(acc[i][j][hh * 2 + 1] - mnew);
                st += __shfl_xor_sync(0xffffffffu, st, 1);
                st += __shfl_xor_sync(0xffffffffu, st, 2);
                rs[i][hh] = rs[i][hh] * __expf(rm[i][hh] - mnew) + st;
                rm[i][hh] = mnew;
            }
        }
    }

    if (tig == 0) {
#pragma unroll
        for (int i = 0; i < 2; i++)
#pragma unroll
            for (int hh = 0; hh < 2; hh++) {
                const int r = wm * 32 + i * 16 + g + hh * 8;
                redM[r * 2 + wn] = rm[i][hh];
                redS[r * 2 + wn] = rs[i][hh];
            }
    }
    __syncthreads();
    if (t < 128) {
        const float m0 = redM[t * 2], m1 = redM[t * 2 + 1];
        const float m = fmaxf(m0, m1);
        const float s = redS[t * 2] * __expf(m0 - m) + redS[t * 2 + 1] * __expf(m1 - m);
        rowM[(size_t)bh * S + q0 + t] = m;
        rowInv[(size_t)bh * S + q0 + t] = 1.0f / s;
    }
}

// ============================================================================
// av_fused (cp.async pipelined, FA2-style register reuse)
// ============================================================================
namespace {
constexpr int AF_QHI = 0;
constexpr int AF_QLO = 128 * KPS;
constexpr int AF_KHI = 2 * 128 * KPS;
constexpr int AF_KLO = AF_KHI + 64 * KPS;
constexpr int AF_VHI = AF_KLO + 64 * KPS;
constexpr int AF_VLO = AF_VHI + 64 * KPS;
constexpr int AF_RM  = AF_VLO + 64 * KPS;
constexpr int AF_RI  = AF_RM + 128;
constexpr int AF_STK = AF_RI + 128;                 // 4096 floats raw K
constexpr int AF_STV = AF_STK + 4096;               // 4096 floats raw V
constexpr int SMEM_AF = (AF_STV + 4096) * 4;        // 107,520 bytes
constexpr int BSTEP = 16 * KPS * 4;
}

__global__ void __launch_bounds__(256, 2) av_fused(
    const float* __restrict__ Q, const float* __restrict__ K,
    const float* __restrict__ V,
    const int* __restrict__ mask, const float* __restrict__ is_org,
    const float* __restrict__ Worg, const float* __restrict__ borg,
    const float* __restrict__ rowM, const float* __restrict__ rowInv,
    float* __restrict__ att, float* __restrict__ C)
{
    extern __shared__ uint32_t smu[];
    uint32_t* Qhi = smu + AF_QHI;
    uint32_t* Qlo = smu + AF_QLO;
    uint32_t* Khi = smu + AF_KHI;
    uint32_t* Klo = smu + AF_KLO;
    uint32_t* Vhi = smu + AF_VHI;
    uint32_t* Vlo = smu + AF_VLO;
    float*    Rm  = reinterpret_cast<float*>(smu + AF_RM);
    float*    Ri  = reinterpret_cast<float*>(smu + AF_RI);
    float*    stK = reinterpret_cast<float*>(smu + AF_STK);
    float*    stV = reinterpret_cast<float*>(smu + AF_STV);
    const uint32_t stKa = smaddr(stK), stVa = smaddr(stV);

    const int t = threadIdx.x, lane = t & 31, wid = t >> 5;
    const int g = lane >> 2, tig = lane & 3;
    const int bh = blockIdx.y, b = bh >> 3, h = bh & 7;
    const int q0 = blockIdx.x * 128;

    const float* Qg = Q + ((size_t)(b * S + q0)) * D + h * DK;
    const float* Kg = K + ((size_t)(b * S)) * D + h * DK;
    const float* Vg = V + ((size_t)(b * S)) * D + h * DK;

    // Issue cp.async for tile 0 (K and V) ASAP
#pragma unroll
    for (int i = t; i < 1024; i += 256) {
        const int row = i >> 4, c4 = (i & 15) * 4;
        cp_async16(stKa + (uint32_t)(row * 64 + c4) * 4u, Kg + (size_t)row * D + c4);
        cp_async16(stVa + (uint32_t)(row * 64 + c4) * 4u, Vg + (size_t)row * D + c4);
    }
    CP_COMMIT();

    if (t < 128) {
        Rm[t] = rowM[(size_t)bh * S + q0 + t];
        Ri[t] = rowInv[(size_t)bh * S + q0 + t];
    }
#pragma unroll
    for (int i = t; i < 2048; i += 256) {
        const int row = i >> 4, c4 = (i & 15) * 4, p = c4 >> 1;
        float4 qv = *reinterpret_cast<const float4*>(Qg + (size_t)row * D + c4);
        uint2 h2, l2;
        split_bf16x2(qv.x, qv.y, h2.x, l2.x);
        split_bf16x2(qv.z, qv.w, h2.y, l2.y);
        *reinterpret_cast<uint2*>(&Qhi[row * KPS + p]) = h2;
        *reinterpret_cast<uint2*>(&Qlo[row * KPS + p]) = l2;
    }

    const int am = lane >> 3, arm = lane & 7;
    uint32_t aQhi, aQlo;
    {
        const int row = wid * 16 + (am & 1) * 8 + arm;
        const uint32_t off = (uint32_t)(row * KPS + (am >> 1) * 4) * 4u;
        aQhi = smaddr(Qhi) + off;
        aQlo = smaddr(Qlo) + off;
    }
    uint32_t bKhi, bKlo, bVhi, bVlo;
    {
        const int brow = ((lane >> 4) & 1) * 8 + (lane & 7);
        const int bkp  = ((lane >> 3) & 1) * 4;
        const uint32_t off = (uint32_t)(brow * KPS + bkp) * 4u;
        bKhi = smaddr(Khi) + off; bKlo = smaddr(Klo) + off;
        bVhi = smaddr(Vhi) + off; bVlo = smaddr(Vlo) + off;
    }

    const float worg = __ldg(Worg + h), bog = __ldg(borg + h);
    const int r0 = wid * 16 + g;
    float og0 = __ldg(is_org + b * S + q0 + r0) * worg + bog;
    float og1 = __ldg(is_org + b * S + q0 + r0 + 8) * worg + bog;

    __syncthreads();
    const float M0 = Rm[r0], I0 = Ri[r0];
    const float M1 = Rm[r0 + 8], I1 = Ri[r0 + 8];

    float accAV[8][4] = {};

    for (int kt = 0; kt < 32; kt++) {
        CP_WAIT0();
        __syncthreads();                 // stage ready; prior MMA readers done

        // Split stage K -> Khi/Klo
#pragma unroll
        for (int i = t; i < 1024; i += 256) {
            const int row = i >> 4, c4 = (i & 15) * 4, p = c4 >> 1;
            float4 kv = *reinterpret_cast<const float4*>(stK + row * 64 + c4);
            uint2 h2, l2;
            split_bf16x2(kv.x, kv.y, h2.x, l2.x);
            split_bf16x2(kv.z, kv.w, h2.y, l2.y);
            *reinterpret_cast<uint2*>(&Khi[row * KPS + p]) = h2;
            *reinterpret_cast<uint2*>(&Klo[row * KPS + p]) = l2;
        }
        // Split+transpose stage V -> Vhi/Vlo ([d][kp])
#pragma unroll
        for (int i = t; i < 512; i += 256) {
            const int dg = i & 15, kp = i >> 4;
            const float* vp = stV + (2 * kp) * 64 + dg * 4;
            float4 va = *reinterpret_cast<const float4*>(vp);
            float4 vb = *reinterpret_cast<const float4*>(vp + 64);
            uint32_t hi, lo;
            split_bf16x2(va.x, vb.x, hi, lo);
            Vhi[(dg * 4 + 0) * KPS + kp] = hi; Vlo[(dg * 4 + 0) * KPS + kp] = lo;
            split_bf16x2(va.y, vb.y, hi, lo);
            Vhi[(dg * 4 + 1) * KPS + kp] = hi; Vlo[(dg * 4 + 1) * KPS + kp] = lo;
            split_bf16x2(va.z, vb.z, hi, lo);
            Vhi[(dg * 4 + 2) * KPS + kp] = hi; Vlo[(dg * 4 + 2) * KPS + kp] = lo;
            split_bf16x2(va.w, vb.w, hi, lo);
            Vhi[(dg * 4 + 3) * KPS + kp] = hi; Vlo[(dg * 4 + 3) * KPS + kp] = lo;
        }
        __syncthreads();

        // Prefetch next tile's K/V under the MMAs
        if (kt < 31) {
#pragma unroll
            for (int i = t; i < 1024; i += 256) {
                const int row = i >> 4, c4 = (i & 15) * 4;
                cp_async16(stKa + (uint32_t)(row * 64 + c4) * 4u,
                           Kg + (size_t)((kt + 1) * 64 + row) * D + c4);
                cp_async16(stVa + (uint32_t)(row * 64 + c4) * 4u,
                           Vg + (size_t)((kt + 1) * 64 + row) * D + c4);
            }
            CP_COMMIT();
        }

        // QK
        float acc[8][4] = {};
#pragma unroll
        for (int ks = 0; ks < 4; ks++) {
            const uint32_t ko = ks * 32u;
            uint32_t ah[4], al[4];
            ldmx4(ah, aQhi + ko);
            ldmx4(al, aQlo + ko);
#pragma unroll
            for (int jp = 0; jp < 4; jp++) {
                uint32_t bhv[4], blv[4];
                ldmx4(bhv, bKhi + jp * BSTEP + ko);
                ldmx4(blv, bKlo + jp * BSTEP + ko);
                mma_bf16(acc[2 * jp],     ah, bhv);
                mma_bf16(acc[2 * jp],     al, bhv);
                mma_bf16(acc[2 * jp],     ah, blv);
                mma_bf16(acc[2 * jp + 1], ah, bhv + 2);
                mma_bf16(acc[2 * jp + 1], al, bhv + 2);
                mma_bf16(acc[2 * jp + 1], ah, blv + 2);
            }
        }

        // Softmax epilogue: p = exp(x - M) * Inv; write p to att; keep in acc
        float* arow0 = &att[((size_t)bh * S + q0 + r0) * S + kt * 64 + 2 * tig];
        float* arow1 = arow0 + 8 * S;
#pragma unroll
        for (int j = 0; j < 8; j++) {
            const int2 mj = *reinterpret_cast<const int2*>(
                mask + b * S + kt * 64 + j * 8 + 2 * tig);
            float x0 = acc[j][0] * 0.125f + og0;
            float x1 = acc[j][1] * 0.125f + og0;
            float x2 = acc[j][2] * 0.125f + og1;
            float x3 = acc[j][3] * 0.125f + og1;
            x0 = mj.x ? x0 : -1e9f;
            x1 = mj.y ? x1 : -1e9f;
            x2 = mj.x ? x2 : -1e9f;
            x3 = mj.y ? x3 : -1e9f;
            const float p0 = __expf(x0 - M0) * I0;
            const float p1 = __expf(x1 - M0) * I0;
            const float p2 = __expf(x2 - M1) * I1;
            const float p3 = __expf(x3 - M1) * I1;
            float2 o;
            o.x = p0; o.y = p1;
            *reinterpret_cast<float2*>(arow0 + j * 8) = o;
            o.x = p2; o.y = p3;
            *reinterpret_cast<float2*>(arow1 + j * 8) = o;
            acc[j][0] = p0; acc[j][1] = p1; acc[j][2] = p2; acc[j][3] = p3;
        }

        // PV
#pragma unroll
        for (int jj = 0; jj < 4; jj++) {
            uint32_t ph[4], pl[4];
            split_bf16x2(acc[2 * jj][0],     acc[2 * jj][1],     ph[0], pl[0]);
            split_bf16x2(acc[2 * jj][2],     acc[2 * jj][3],     ph[1], pl[1]);
            split_bf16x2(acc[2 * jj + 1][0], acc[2 * jj + 1][1], ph[2], pl[2]);
            split_bf16x2(acc[2 * jj + 1][2], acc[2 * jj + 1][3], ph[3], pl[3]);
            const uint32_t ko = jj * 32u;
#pragma unroll
            for (int dp = 0; dp < 4; dp++) {
                uint32_t vh[4], vl[4];
                ldmx4(vh, bVhi + dp * BSTEP + ko);
                ldmx4(vl, bVlo + dp * BSTEP + ko);
                mma_bf16(accAV[2 * dp],     ph, vh);
                mma_bf16(accAV[2 * dp],     pl, vh);
                mma_bf16(accAV[2 * dp],     ph, vl);
                mma_bf16(accAV[2 * dp + 1], ph, vh + 2);
                mma_bf16(accAV[2 * dp + 1], pl, vh + 2);
                mma_bf16(accAV[2 * dp + 1], ph, vl + 2);
            }
        }
    }

    // Store context C
#pragma unroll
    for (int dj = 0; dj < 8; dj++) {
        const int col = h * DK + dj * 8 + 2 * tig;
        float2 o;
        o.x = accAV[dj][0]; o.y = accAV[dj][1];
        *reinterpret_cast<float2*>(&C[(size_t)(b * S + q0 + r0) * D + col]) = o;
        o.x = accAV[dj][2]; o.y = accAV[dj][3];
        *reinterpret_cast<float2*>(&C[(size_t)(b * S + q0 + r0 + 8) * D + col]) = o;
    }
}

// ---------------------------------------------------------------------------
extern "C" void kernel_launch(void* const* d_in, const int* in_sizes, int n_in,
                              void* d_out, int out_size)
{
    const float* query = (const float*)d_in[0];
    const float* key   = (const float*)d_in[1];
    const float* value = (const float*)d_in[2];
    const int*   mask  = (const int*)d_in[3];
    const float* isog  = (const float*)d_in[4];
    const float* Wq    = (const float*)d_in[5];
    const float* bq    = (const float*)d_in[6];
    const float* Wk    = (const float*)d_in[7];
    const float* bk    = (const float*)d_in[8];
    const float* Wv    = (const float*)d_in[9];
    const float* bv    = (const float*)d_in[10];
    const float* Wo    = (const float*)d_in[11];
    const float* bo    = (const float*)d_in[12];
    const float* Worg  = (const float*)d_in[13];
    const float* borg  = (const float*)d_in[14];

    float* out = (float*)d_out;

    float *qbuf, *kbuf, *vbuf, *cbuf, *rowM, *rowInv;
    cudaGetSymbolAddress((void**)&qbuf, g_Q);
    cudaGetSymbolAddress((void**)&kbuf, g_K);
    cudaGetSymbolAddress((void**)&vbuf, g_V);
    cudaGetSymbolAddress((void**)&cbuf, g_C);
    cudaGetSymbolAddress((void**)&rowM, g_rowM);
    cudaGetSymbolAddress((void**)&rowInv, g_rowInv);

    const long long OUT_MAIN = (long long)B * S * D;
    const long long ATT_SZ   = (long long)B * H * S * S;
    float* att;
    if ((long long)out_size >= OUT_MAIN + ATT_SZ) {
        att = out + OUT_MAIN;
    } else {
        cudaGetSymbolAddress((void**)&att, g_att);
    }

    static bool attr_done = false;
    if (!attr_done) {
        cudaFuncSetAttribute(gemm_mma,  cudaFuncAttributeMaxDynamicSharedMemorySize, SMEM_GEMM);
        cudaFuncSetAttribute(stats_mma, cudaFuncAttributeMaxDynamicSharedMemorySize, SMEM_STATS);
        cudaFuncSetAttribute(av_fused,  cudaFuncAttributeMaxDynamicSharedMemorySize, SMEM_AF);
        attr_done = true;
    }

    dim3 gg(4, 64);
    gemm_mma<<<gg, 256, SMEM_GEMM>>>(query, Wq, bq, qbuf);
    gemm_mma<<<gg, 256, SMEM_GEMM>>>(key,   Wk, bk, kbuf);
    gemm_mma<<<gg, 256, SMEM_GEMM>>>(value, Wv, bv, vbuf);

    dim3 gf(S / 128, B * H);
    stats_mma<<<gf, 256, SMEM_STATS>>>(qbuf, kbuf, mask, isog, Worg, borg, rowM, rowInv);

    av_fused<<<gf, 256, SMEM_AF>>>(qbuf, kbuf, vbuf, mask, isog, Worg, borg,
                                   rowM, rowInv, att, cbuf);

    gemm_mma<<<gg, 256, SMEM_GEMM>>>(cbuf, Wo, bo, out);
}

// round 13
// speedup vs baseline: 1.0181x; 1.0181x over previous
#include <cuda_runtime.h>
#include <cstdint>

namespace {
constexpr int B = 4, S = 2048, D = 512, H = 8, DK = 64;
constexpr int DP = D / 2;   // 256 bf16x2 pairs per row
}

// Scratch (allocation-free rule: __device__ globals)
__device__ uint32_t g_Qhi[(size_t)B * S * DP];
__device__ uint32_t g_Qlo[(size_t)B * S * DP];
__device__ uint32_t g_Khi[(size_t)B * S * DP];
__device__ uint32_t g_Klo[(size_t)B * S * DP];
__device__ uint32_t g_Vhi[(size_t)B * S * DP];
__device__ uint32_t g_Vlo[(size_t)B * S * DP];
__device__ float    g_C[(size_t)B * S * D];
__device__ float    g_att[(size_t)B * H * S * S];
__device__ float    g_rowM[(size_t)B * H * S];
__device__ float    g_rowInv[(size_t)B * H * S];

// ============================================================================
// bf16 split, MMA, ldmatrix helpers (portable PTX — works on compute_103)
// ============================================================================
__device__ __forceinline__ void split_bf16x2(float x0, float x1, uint32_t& hi, uint32_t& lo) {
    asm("cvt.rn.bf16x2.f32 %0, %1, %2;" : "=r"(hi) : "f"(x1), "f"(x0));
    const float h0 = __uint_as_float(hi << 16);
    const float h1 = __uint_as_float(hi & 0xFFFF0000u);
    asm("cvt.rn.bf16x2.f32 %0, %1, %2;" : "=r"(lo) : "f"(x1 - h1), "f"(x0 - h0));
}
__device__ __forceinline__ void mma_bf16(float c[4], const uint32_t a[4], const uint32_t b[2]) {
    asm volatile(
        "mma.sync.aligned.m16n8k16.row.col.f32.bf16.bf16.f32 "
        "{%0,%1,%2,%3}, {%4,%5,%6,%7}, {%8,%9}, {%0,%1,%2,%3};"
        : "+f"(c[0]), "+f"(c[1]), "+f"(c[2]), "+f"(c[3])
        : "r"(a[0]), "r"(a[1]), "r"(a[2]), "r"(a[3]), "r"(b[0]), "r"(b[1]));
}
__device__ __forceinline__ void ldmx4(uint32_t r[4], uint32_t addr) {
    asm volatile("ldmatrix.sync.aligned.m8n8.x4.shared.b16 {%0,%1,%2,%3}, [%4];"
                 : "=r"(r[0]), "=r"(r[1]), "=r"(r[2]), "=r"(r[3]) : "r"(addr));
}
__device__ __forceinline__ void ldmx2(uint32_t r[2], uint32_t addr) {
    asm volatile("ldmatrix.sync.aligned.m8n8.x2.shared.b16 {%0,%1}, [%2];"
                 : "=r"(r[0]), "=r"(r[1]) : "r"(addr));
}
__device__ __forceinline__ uint32_t smaddr(const void* p) {
    return (uint32_t)__cvta_generic_to_shared(p);
}

namespace {
constexpr int KPS = 36;   // bf16x2-pair stride (padded; conflict-free)
}

// ============================================================================
// Projection GEMM (bf16 3-term): Y = X @ W^T + bias.
// SPLIT=true  -> write pre-split bf16 hi/lo pair buffers (for Q/K/V)
// SPLIT=false -> write fp32 (final output projection)
// ============================================================================
namespace {
constexpr int GM_XHI = 0;
constexpr int GM_XLO = 128 * KPS;
constexpr int GM_WHI = 2 * 128 * KPS;
constexpr int GM_WLO = 3 * 128 * KPS;
constexpr int SMEM_GEMM = 4 * 128 * KPS * 4;     // 73,728 bytes
}

template <bool SPLIT>
__global__ void __launch_bounds__(256, 2) gemm_mma_t(
    const float* __restrict__ X, const float* __restrict__ W,
    const float* __restrict__ bias, float* __restrict__ Y,
    uint32_t* __restrict__ Yhi, uint32_t* __restrict__ Ylo)
{
    extern __shared__ uint32_t smu[];
    uint32_t* Xhi = smu + GM_XHI;
    uint32_t* Xlo = smu + GM_XLO;
    uint32_t* Whi = smu + GM_WHI;
    uint32_t* Wlo = smu + GM_WLO;

    const int t = threadIdx.x, lane = t & 31, wid = t >> 5;
    const int g = lane >> 2, tig = lane & 3;
    const int wm = wid & 1, wn = wid >> 1;
    const int m0 = blockIdx.y * 128, n0 = blockIdx.x * 128;

    const int am = lane >> 3, arm = lane & 7;
    const int bmat = (lane >> 3) & 1, brm = lane & 7;
    uint32_t aHi[4], aLo[4], bHi[4], bLo[4];
#pragma unroll
    for (int i = 0; i < 4; i++) {
        const int row = wm * 64 + i * 16 + (am & 1) * 8 + arm;
        const uint32_t off = (uint32_t)(row * KPS + (am >> 1) * 4) * 4u;
        aHi[i] = smaddr(Xhi) + off;
        aLo[i] = smaddr(Xlo) + off;
    }
#pragma unroll
    for (int j = 0; j < 4; j++) {
        const int row = wn * 32 + j * 8 + brm;
        const uint32_t off = (uint32_t)(row * KPS + bmat * 4) * 4u;
        bHi[j] = smaddr(Whi) + off;
        bLo[j] = smaddr(Wlo) + off;
    }

    float acc[4][4][4] = {};

    for (int kc = 0; kc < 512; kc += 64) {
#pragma unroll
        for (int i = t; i < 2048; i += 256) {
            const int row = i >> 4, c4 = (i & 15) * 4, p = c4 >> 1;
            float4 xv = *reinterpret_cast<const float4*>(&X[(size_t)(m0 + row) * 512 + kc + c4]);
            float4 wv = *reinterpret_cast<const float4*>(&W[(size_t)(n0 + row) * 512 + kc + c4]);
            uint2 h, l;
            split_bf16x2(xv.x, xv.y, h.x, l.x);
            split_bf16x2(xv.z, xv.w, h.y, l.y);
            *reinterpret_cast<uint2*>(&Xhi[row * KPS + p]) = h;
            *reinterpret_cast<uint2*>(&Xlo[row * KPS + p]) = l;
            split_bf16x2(wv.x, wv.y, h.x, l.x);
            split_bf16x2(wv.z, wv.w, h.y, l.y);
            *reinterpret_cast<uint2*>(&Whi[row * KPS + p]) = h;
            *reinterpret_cast<uint2*>(&Wlo[row * KPS + p]) = l;
        }
        __syncthreads();

#pragma unroll
        for (int ks = 0; ks < 4; ks++) {
            const uint32_t ko = ks * 32u;
            uint32_t ahi[4][4], alo[4][4];
#pragma unroll
            for (int i = 0; i < 4; i++) {
                ldmx4(ahi[i], aHi[i] + ko);
                ldmx4(alo[i], aLo[i] + ko);
            }
#pragma unroll
            for (int j = 0; j < 4; j++) {
                uint32_t bhi[2], blo[2];
                ldmx2(bhi, bHi[j] + ko);
                ldmx2(blo, bLo[j] + ko);
#pragma unroll
                for (int i = 0; i < 4; i++) {
                    mma_bf16(acc[i][j], ahi[i], bhi);
                    mma_bf16(acc[i][j], alo[i], bhi);
                    mma_bf16(acc[i][j], ahi[i], blo);
                }
            }
        }
        __syncthreads();
    }

#pragma unroll
    for (int i = 0; i < 4; i++) {
        const int row0 = m0 + wm * 64 + i * 16 + g;
#pragma unroll
        for (int j = 0; j < 4; j++) {
            const int col = n0 + wn * 32 + j * 8 + 2 * tig;
            const float b0 = __ldg(bias + col), b1 = __ldg(bias + col + 1);
            if (SPLIT) {
                const int pr = col >> 1;
                uint32_t hi, lo;
                split_bf16x2(acc[i][j][0] + b0, acc[i][j][1] + b1, hi, lo);
                Yhi[(size_t)row0 * DP + pr] = hi;
                Ylo[(size_t)row0 * DP + pr] = lo;
                split_bf16x2(acc[i][j][2] + b0, acc[i][j][3] + b1, hi, lo);
                Yhi[(size_t)(row0 + 8) * DP + pr] = hi;
                Ylo[(size_t)(row0 + 8) * DP + pr] = lo;
            } else {
                float2 o;
                o.x = acc[i][j][0] + b0; o.y = acc[i][j][1] + b1;
                *reinterpret_cast<float2*>(&Y[(size_t)row0 * 512 + col]) = o;
                o.x = acc[i][j][2] + b0; o.y = acc[i][j][3] + b1;
                *reinterpret_cast<float2*>(&Y[(size_t)(row0 + 8) * 512 + col]) = o;
            }
        }
    }
}

// ============================================================================
// stats_mma: online (max, sumexp) -> rowM, rowInv.
// Tiles loaded as PRE-SPLIT uint copies (no per-tile cvt work).
// ============================================================================
namespace {
constexpr int ST_QHI = 0;
constexpr int ST_QLO = 128 * KPS;
constexpr int ST_KHI = 2 * 128 * KPS;
constexpr int ST_KLO = ST_KHI + 64 * KPS;
constexpr int ST_RED = ST_KLO + 64 * KPS;
constexpr int SMEM_STATS = (ST_RED + 512) * 4;      // 57,344 bytes
}

__global__ void __launch_bounds__(256, 2) stats_mma(
    const uint32_t* __restrict__ Qhg, const uint32_t* __restrict__ Qlg,
    const uint32_t* __restrict__ Khg, const uint32_t* __restrict__ Klg,
    const int* __restrict__ mask, const float* __restrict__ is_org,
    const float* __restrict__ Worg, const float* __restrict__ borg,
    float* __restrict__ rowM, float* __restrict__ rowInv)
{
    extern __shared__ uint32_t smu[];
    uint32_t* Qhi = smu + ST_QHI;
    uint32_t* Qlo = smu + ST_QLO;
    uint32_t* Khi = smu + ST_KHI;
    uint32_t* Klo = smu + ST_KLO;
    float* redM = reinterpret_cast<float*>(smu + ST_RED);
    float* redS = redM + 256;

    const int t = threadIdx.x, lane = t & 31, wid = t >> 5;
    const int g = lane >> 2, tig = lane & 3;
    const int wm = wid & 3, wn = wid >> 2;
    const int bh = blockIdx.y, b = bh >> 3, h = bh & 7;
    const int q0 = blockIdx.x * 128;

    const uint32_t* Qh = Qhg + ((size_t)(b * S + q0)) * DP + h * 32;
    const uint32_t* Ql = Qlg + ((size_t)(b * S + q0)) * DP + h * 32;
    const uint32_t* Kh = Khg + ((size_t)(b * S)) * DP + h * 32;
    const uint32_t* Kl = Klg + ((size_t)(b * S)) * DP + h * 32;

    // Q strip copy (pre-split): 128 rows x 32 pairs
#pragma unroll
    for (int i = t; i < 1024; i += 256) {
        const int row = i >> 3, p4 = (i & 7) * 4;
        *reinterpret_cast<uint4*>(&Qhi[row * KPS + p4]) =
            *reinterpret_cast<const uint4*>(Qh + (size_t)row * DP + p4);
        *reinterpret_cast<uint4*>(&Qlo[row * KPS + p4]) =
            *reinterpret_cast<const uint4*>(Ql + (size_t)row * DP + p4);
    }

    const int am = lane >> 3, arm = lane & 7;
    const int bmat = (lane >> 3) & 1, brm = lane & 7;
    uint32_t aHi[2], aLo[2], bHi[4], bLo[4];
#pragma unroll
    for (int i = 0; i < 2; i++) {
        const int row = wm * 32 + i * 16 + (am & 1) * 8 + arm;
        const uint32_t off = (uint32_t)(row * KPS + (am >> 1) * 4) * 4u;
        aHi[i] = smaddr(Qhi) + off;
        aLo[i] = smaddr(Qlo) + off;
    }
#pragma unroll
    for (int j = 0; j < 4; j++) {
        const int row = wn * 32 + j * 8 + brm;
        const uint32_t off = (uint32_t)(row * KPS + bmat * 4) * 4u;
        bHi[j] = smaddr(Khi) + off;
        bLo[j] = smaddr(Klo) + off;
    }

    const float worg = __ldg(Worg + h), bog = __ldg(borg + h);
    float og[2][2];
#pragma unroll
    for (int i = 0; i < 2; i++)
#pragma unroll
        for (int hh = 0; hh < 2; hh++)
            og[i][hh] = __ldg(is_org + b * S + q0 + wm * 32 + i * 16 + g + hh * 8) * worg + bog;

    float rm[2][2], rs[2][2];
#pragma unroll
    for (int i = 0; i < 2; i++)
#pragma unroll
        for (int hh = 0; hh < 2; hh++) { rm[i][hh] = -1e30f; rs[i][hh] = 0.0f; }

    for (int kt = 0; kt < 32; kt++) {
        // K tile copy (pre-split): 64 rows x 32 pairs
#pragma unroll
        for (int i = t; i < 512; i += 256) {
            const int row = i >> 3, p4 = (i & 7) * 4;
            *reinterpret_cast<uint4*>(&Khi[row * KPS + p4]) =
                *reinterpret_cast<const uint4*>(Kh + (size_t)(kt * 64 + row) * DP + p4);
            *reinterpret_cast<uint4*>(&Klo[row * KPS + p4]) =
                *reinterpret_cast<const uint4*>(Kl + (size_t)(kt * 64 + row) * DP + p4);
        }
        __syncthreads();

        float acc[2][4][4] = {};
#pragma unroll
        for (int ks = 0; ks < 4; ks++) {
            const uint32_t ko = ks * 32u;
            uint32_t ahi[2][4], alo[2][4];
#pragma unroll
            for (int i = 0; i < 2; i++) { ldmx4(ahi[i], aHi[i] + ko); ldmx4(alo[i], aLo[i] + ko); }
#pragma unroll
            for (int j = 0; j < 4; j++) {
                uint32_t bhi[2], blo[2];
                ldmx2(bhi, bHi[j] + ko);
                ldmx2(blo, bLo[j] + ko);
#pragma unroll
                for (int i = 0; i < 2; i++) {
                    mma_bf16(acc[i][j], ahi[i], bhi);
                    mma_bf16(acc[i][j], alo[i], bhi);
                    mma_bf16(acc[i][j], ahi[i], blo);
                }
            }
        }

        int2 mj[4];
#pragma unroll
        for (int j = 0; j < 4; j++)
            mj[j] = *reinterpret_cast<const int2*>(mask + b * S + kt * 64 + wn * 32 + j * 8 + 2 * tig);

#pragma unroll
        for (int i = 0; i < 2; i++) {
#pragma unroll
            for (int j = 0; j < 4; j++) {
                float v;
                v = acc[i][j][0] * 0.125f + og[i][0]; acc[i][j][0] = mj[j].x ? v : -1e9f;
                v = acc[i][j][1] * 0.125f + og[i][0]; acc[i][j][1] = mj[j].y ? v : -1e9f;
                v = acc[i][j][2] * 0.125f + og[i][1]; acc[i][j][2] = mj[j].x ? v : -1e9f;
                v = acc[i][j][3] * 0.125f + og[i][1]; acc[i][j][3] = mj[j].y ? v : -1e9f;
            }
        }

#pragma unroll
        for (int i = 0; i < 2; i++) {
#pragma unroll
            for (int hh = 0; hh < 2; hh++) {
                float mt = -1e30f;
#pragma unroll
                for (int j = 0; j < 4; j++)
                    mt = fmaxf(mt, fmaxf(acc[i][j][hh * 2], acc[i][j][hh * 2 + 1]));
                mt = fmaxf(mt, __shfl_xor_sync(0xffffffffu, mt, 1));
                mt = fmaxf(mt, __shfl_xor_sync(0xffffffffu, mt, 2));
                const float mnew = fmaxf(rm[i][hh], mt);
                float st = 0.0f;
#pragma unroll
                for (int j = 0; j < 4; j++)
                    st += __expf(acc[i][j][hh * 2] - mnew) + __expf(acc[i][j][hh * 2 + 1] - mnew);
                st += __shfl_xor_sync(0xffffffffu, st, 1);
                st += __shfl_xor_sync(0xffffffffu, st, 2);
                rs[i][hh] = rs[i][hh] * __expf(rm[i][hh] - mnew) + st;
                rm[i][hh] = mnew;
            }
        }
        __syncthreads();
    }

    if (tig == 0) {
#pragma unroll
        for (int i = 0; i < 2; i++)
#pragma unroll
            for (int hh = 0; hh < 2; hh++) {
                const int r = wm * 32 + i * 16 + g + hh * 8;
                redM[r * 2 + wn] = rm[i][hh];
                redS[r * 2 + wn] = rs[i][hh];
            }
    }
    __syncthreads();
    if (t < 128) {
        const float m0 = redM[t * 2], m1 = redM[t * 2 + 1];
        const float m = fmaxf(m0, m1);
        const float s = redS[t * 2] * __expf(m0 - m) + redS[t * 2 + 1] * __expf(m1 - m);
        rowM[(size_t)bh * S + q0 + t] = m;
        rowInv[(size_t)bh * S + q0 + t] = 1.0f / s;
    }
}

// ============================================================================
// av_fused (FA2-style register reuse; pre-split tile copies, PRMT V-transpose)
// ============================================================================
namespace {
constexpr int AF_QHI = 0;
constexpr int AF_QLO = 128 * KPS;
constexpr int AF_KHI = 2 * 128 * KPS;
constexpr int AF_KLO = AF_KHI + 64 * KPS;
constexpr int AF_VHI = AF_KLO + 64 * KPS;
constexpr int AF_VLO = AF_VHI + 64 * KPS;
constexpr int AF_RM  = AF_VLO + 64 * KPS;
constexpr int AF_RI  = AF_RM + 128;
constexpr int SMEM_AF = (AF_RI + 128) * 4;     // 74,752 bytes
constexpr int BSTEP = 16 * KPS * 4;
}

__global__ void __launch_bounds__(256, 2) av_fused(
    const uint32_t* __restrict__ Qhg, const uint32_t* __restrict__ Qlg,
    const uint32_t* __restrict__ Khg, const uint32_t* __restrict__ Klg,
    const uint32_t* __restrict__ Vhg, const uint32_t* __restrict__ Vlg,
    const int* __restrict__ mask, const float* __restrict__ is_org,
    const float* __restrict__ Worg, const float* __restrict__ borg,
    const float* __restrict__ rowM, const float* __restrict__ rowInv,
    float* __restrict__ att, float* __restrict__ C)
{
    extern __shared__ uint32_t smu[];
    uint32_t* Qhi = smu + AF_QHI;
    uint32_t* Qlo = smu + AF_QLO;
    uint32_t* Khi = smu + AF_KHI;
    uint32_t* Klo = smu + AF_KLO;
    uint32_t* Vhi = smu + AF_VHI;
    uint32_t* Vlo = smu + AF_VLO;
    float*    Rm  = reinterpret_cast<float*>(smu + AF_RM);
    float*    Ri  = reinterpret_cast<float*>(smu + AF_RI);

    const int t = threadIdx.x, lane = t & 31, wid = t >> 5;
    const int g = lane >> 2, tig = lane & 3;
    const int bh = blockIdx.y, b = bh >> 3, h = bh & 7;
    const int q0 = blockIdx.x * 128;

    const uint32_t* Qh = Qhg + ((size_t)(b * S + q0)) * DP + h * 32;
    const uint32_t* Ql = Qlg + ((size_t)(b * S + q0)) * DP + h * 32;
    const uint32_t* Kh = Khg + ((size_t)(b * S)) * DP + h * 32;
    const uint32_t* Kl = Klg + ((size_t)(b * S)) * DP + h * 32;
    const uint32_t* Vh = Vhg + ((size_t)(b * S)) * DP + h * 32;
    const uint32_t* Vl = Vlg + ((size_t)(b * S)) * DP + h * 32;

    if (t < 128) {
        Rm[t] = rowM[(size_t)bh * S + q0 + t];
        Ri[t] = rowInv[(size_t)bh * S + q0 + t];
    }
    // Q strip copy (pre-split)
#pragma unroll
    for (int i = t; i < 1024; i += 256) {
        const int row = i >> 3, p4 = (i & 7) * 4;
        *reinterpret_cast<uint4*>(&Qhi[row * KPS + p4]) =
            *reinterpret_cast<const uint4*>(Qh + (size_t)row * DP + p4);
        *reinterpret_cast<uint4*>(&Qlo[row * KPS + p4]) =
            *reinterpret_cast<const uint4*>(Ql + (size_t)row * DP + p4);
    }

    const int am = lane >> 3, arm = lane & 7;
    uint32_t aQhi, aQlo;
    {
        const int row = wid * 16 + (am & 1) * 8 + arm;
        const uint32_t off = (uint32_t)(row * KPS + (am >> 1) * 4) * 4u;
        aQhi = smaddr(Qhi) + off;
        aQlo = smaddr(Qlo) + off;
    }
    uint32_t bKhi, bKlo, bVhi, bVlo;
    {
        const int brow = ((lane >> 4) & 1) * 8 + (lane & 7);
        const int bkp  = ((lane >> 3) & 1) * 4;
        const uint32_t off = (uint32_t)(brow * KPS + bkp) * 4u;
        bKhi = smaddr(Khi) + off; bKlo = smaddr(Klo) + off;
        bVhi = smaddr(Vhi) + off; bVlo = smaddr(Vlo) + off;
    }

    const float worg = __ldg(Worg + h), bog = __ldg(borg + h);
    const int r0 = wid * 16 + g;
    float og0 = __ldg(is_org + b * S + q0 + r0) * worg + bog;
    float og1 = __ldg(is_org + b * S + q0 + r0 + 8) * worg + bog;

    __syncthreads();
    const float M0 = Rm[r0], I0 = Ri[r0];
    const float M1 = Rm[r0 + 8], I1 = Ri[r0 + 8];

    float accAV[8][4] = {};

    for (int kt = 0; kt < 32; kt++) {
        // K tile copy
#pragma unroll
        for (int i = t; i < 512; i += 256) {
            const int row = i >> 3, p4 = (i & 7) * 4;
            *reinterpret_cast<uint4*>(&Khi[row * KPS + p4]) =
                *reinterpret_cast<const uint4*>(Kh + (size_t)(kt * 64 + row) * DP + p4);
            *reinterpret_cast<uint4*>(&Klo[row * KPS + p4]) =
                *reinterpret_cast<const uint4*>(Kl + (size_t)(kt * 64 + row) * DP + p4);
        }
        // V tile transpose via byte_perm: Vsm[d][kp] from packed (d,d+1) pairs
#pragma unroll
        for (int i = t; i < 1024; i += 256) {
            const int dp = i & 31, kp = i >> 5;          // d pair idx, k pair idx
            const size_t goff = (size_t)(kt * 64 + 2 * kp) * DP + dp;
            const uint32_t vah = Vh[goff], vbh = Vh[goff + DP];
            const uint32_t val = Vl[goff], vbl = Vl[goff + DP];
            Vhi[(2 * dp) * KPS + kp]     = __byte_perm(vah, vbh, 0x5410);
            Vhi[(2 * dp + 1) * KPS + kp] = __byte_perm(vah, vbh, 0x7632);
            Vlo[(2 * dp) * KPS + kp]     = __byte_perm(val, vbl, 0x5410);
            Vlo[(2 * dp + 1) * KPS + kp] = __byte_perm(val, vbl, 0x7632);
        }
        __syncthreads();

        // QK
        float acc[8][4] = {};
#pragma unroll
        for (int ks = 0; ks < 4; ks++) {
            const uint32_t ko = ks * 32u;
            uint32_t ah[4], al[4];
            ldmx4(ah, aQhi + ko);
            ldmx4(al, aQlo + ko);
#pragma unroll
            for (int jp = 0; jp < 4; jp++) {
                uint32_t bhv[4], blv[4];
                ldmx4(bhv, bKhi + jp * BSTEP + ko);
                ldmx4(blv, bKlo + jp * BSTEP + ko);
                mma_bf16(acc[2 * jp],     ah, bhv);
                mma_bf16(acc[2 * jp],     al, bhv);
                mma_bf16(acc[2 * jp],     ah, blv);
                mma_bf16(acc[2 * jp + 1], ah, bhv + 2);
                mma_bf16(acc[2 * jp + 1], al, bhv + 2);
                mma_bf16(acc[2 * jp + 1], ah, blv + 2);
            }
        }

        // Softmax epilogue: p = exp(x - M) * Inv; write p to att; keep in acc
        float* arow0 = &att[((size_t)bh * S + q0 + r0) * S + kt * 64 + 2 * tig];
        float* arow1 = arow0 + 8 * S;
#pragma unroll
        for (int j = 0; j < 8; j++) {
            const int2 mj = *reinterpret_cast<const int2*>(
                mask + b * S + kt * 64 + j * 8 + 2 * tig);
            float x0 = acc[j][0] * 0.125f + og0;
            float x1 = acc[j][1] * 0.125f + og0;
            float x2 = acc[j][2] * 0.125f + og1;
            float x3 = acc[j][3] * 0.125f + og1;
            x0 = mj.x ? x0 : -1e9f;
            x1 = mj.y ? x1 : -1e9f;
            x2 = mj.x ? x2 : -1e9f;
            x3 = mj.y ? x3 : -1e9f;
            const float p0 = __expf(x0 - M0) * I0;
            const float p1 = __expf(x1 - M0) * I0;
            const float p2 = __expf(x2 - M1) * I1;
            const float p3 = __expf(x3 - M1) * I1;
            float2 o;
            o.x = p0; o.y = p1;
            *reinterpret_cast<float2*>(arow0 + j * 8) = o;
            o.x = p2; o.y = p3;
            *reinterpret_cast<float2*>(arow1 + j * 8) = o;
            acc[j][0] = p0; acc[j][1] = p1; acc[j][2] = p2; acc[j][3] = p3;
        }

        // PV: A-frags packed directly from acc
#pragma unroll
        for (int jj = 0; jj < 4; jj++) {
            uint32_t ph[4], pl[4];
            split_bf16x2(acc[2 * jj][0],     acc[2 * jj][1],     ph[0], pl[0]);
            split_bf16x2(acc[2 * jj][2],     acc[2 * jj][3],     ph[1], pl[1]);
            split_bf16x2(acc[2 * jj + 1][0], acc[2 * jj + 1][1], ph[2], pl[2]);
            split_bf16x2(acc[2 * jj + 1][2], acc[2 * jj + 1][3], ph[3], pl[3]);
            const uint32_t ko = jj * 32u;
#pragma unroll
            for (int dp = 0; dp < 4; dp++) {
                uint32_t vh[4], vl[4];
                ldmx4(vh, bVhi + dp * BSTEP + ko);
                ldmx4(vl, bVlo + dp * BSTEP + ko);
                mma_bf16(accAV[2 * dp],     ph, vh);
                mma_bf16(accAV[2 * dp],     pl, vh);
                mma_bf16(accAV[2 * dp],     ph, vl);
                mma_bf16(accAV[2 * dp + 1], ph, vh + 2);
                mma_bf16(accAV[2 * dp + 1], pl, vh + 2);
                mma_bf16(accAV[2 * dp + 1], ph, vl + 2);
            }
        }
        __syncthreads();
    }

    // Store context C
#pragma unroll
    for (int dj = 0; dj < 8; dj++) {
        const int col = h * DK + dj * 8 + 2 * tig;
        float2 o;
        o.x = accAV[dj][0]; o.y = accAV[dj][1];
        *reinterpret_cast<float2*>(&C[(size_t)(b * S + q0 + r0) * D + col]) = o;
        o.x = accAV[dj][2]; o.y = accAV[dj][3];
        *reinterpret_cast<float2*>(&C[(size_t)(b * S + q0 + r0 + 8) * D + col]) = o;
    }
}

// ---------------------------------------------------------------------------
extern "C" void kernel_launch(void* const* d_in, const int* in_sizes, int n_in,
                              void* d_out, int out_size)
{
    const float* query = (const float*)d_in[0];
    const float* key   = (const float*)d_in[1];
    const float* value = (const float*)d_in[2];
    const int*   mask  = (const int*)d_in[3];
    const float* isog  = (const float*)d_in[4];
    const float* Wq    = (const float*)d_in[5];
    const float* bq    = (const float*)d_in[6];
    const float* Wk    = (const float*)d_in[7];
    const float* bk    = (const float*)d_in[8];
    const float* Wv    = (const float*)d_in[9];
    const float* bv    = (const float*)d_in[10];
    const float* Wo    = (const float*)d_in[11];
    const float* bo    = (const float*)d_in[12];
    const float* Worg  = (const float*)d_in[13];
    const float* borg  = (const float*)d_in[14];

    float* out = (float*)d_out;

    uint32_t *qhi, *qlo, *khi, *klo, *vhi, *vlo;
    float *cbuf, *rowM, *rowInv;
    cudaGetSymbolAddress((void**)&qhi, g_Qhi);
    cudaGetSymbolAddress((void**)&qlo, g_Qlo);
    cudaGetSymbolAddress((void**)&khi, g_Khi);
    cudaGetSymbolAddress((void**)&klo, g_Klo);
    cudaGetSymbolAddress((void**)&vhi, g_Vhi);
    cudaGetSymbolAddress((void**)&vlo, g_Vlo);
    cudaGetSymbolAddress((void**)&cbuf, g_C);
    cudaGetSymbolAddress((void**)&rowM, g_rowM);
    cudaGetSymbolAddress((void**)&rowInv, g_rowInv);

    const long long OUT_MAIN = (long long)B * S * D;
    const long long ATT_SZ   = (long long)B * H * S * S;
    float* att;
    if ((long long)out_size >= OUT_MAIN + ATT_SZ) {
        att = out + OUT_MAIN;
    } else {
        cudaGetSymbolAddress((void**)&att, g_att);
    }

    static bool attr_done = false;
    if (!attr_done) {
        cudaFuncSetAttribute(gemm_mma_t<true>,  cudaFuncAttributeMaxDynamicSharedMemorySize, SMEM_GEMM);
        cudaFuncSetAttribute(gemm_mma_t<false>, cudaFuncAttributeMaxDynamicSharedMemorySize, SMEM_GEMM);
        cudaFuncSetAttribute(stats_mma, cudaFuncAttributeMaxDynamicSharedMemorySize, SMEM_STATS);
        cudaFuncSetAttribute(av_fused,  cudaFuncAttributeMaxDynamicSharedMemorySize, SMEM_AF);
        attr_done = true;
    }

    dim3 gg(4, 64);
    gemm_mma_t<true><<<gg, 256, SMEM_GEMM>>>(query, Wq, bq, nullptr, qhi, qlo);
    gemm_mma_t<true><<<gg, 256, SMEM_GEMM>>>(key,   Wk, bk, nullptr, khi, klo);
    gemm_mma_t<true><<<gg, 256, SMEM_GEMM>>>(value, Wv, bv, nullptr, vhi, vlo);

    dim3 gf(S / 128, B * H);
    stats_mma<<<gf, 256, SMEM_STATS>>>(qhi, qlo, khi, klo, mask, isog, Worg, borg, rowM, rowInv);

    av_fused<<<gf, 256, SMEM_AF>>>(qhi, qlo, khi, klo, vhi, vlo,
                                   mask, isog, Worg, borg, rowM, rowInv, att, cbuf);

    gemm_mma_t<false><<<gg, 256, SMEM_GEMM>>>(cbuf, Wo, bo, out, nullptr, nullptr);
}

// round 14
// speedup vs baseline: 1.0315x; 1.0132x over previous
#include <cuda_runtime.h>
#include <cstdint>

namespace {
constexpr int B = 4, S = 2048, D = 512, H = 8, DK = 64;
}

// Scratch (allocation-free rule: __device__ globals)
__device__ float g_Q[(size_t)B * S * D];
__device__ float g_K[(size_t)B * S * D];
__device__ float g_V[(size_t)B * S * D];
__device__ float g_C[(size_t)B * S * D];
__device__ float g_att[(size_t)B * H * S * S];
__device__ float g_rowM[(size_t)B * H * S];
__device__ float g_rowInv[(size_t)B * H * S];

// ============================================================================
// bf16 split, MMA, ldmatrix helpers (portable PTX — works on compute_103)
// ============================================================================
__device__ __forceinline__ void split_bf16x2(float x0, float x1, uint32_t& hi, uint32_t& lo) {
    asm("cvt.rn.bf16x2.f32 %0, %1, %2;" : "=r"(hi) : "f"(x1), "f"(x0));
    const float h0 = __uint_as_float(hi << 16);
    const float h1 = __uint_as_float(hi & 0xFFFF0000u);
    asm("cvt.rn.bf16x2.f32 %0, %1, %2;" : "=r"(lo) : "f"(x1 - h1), "f"(x0 - h0));
}
__device__ __forceinline__ void mma_bf16(float c[4], const uint32_t a[4], const uint32_t b[2]) {
    asm volatile(
        "mma.sync.aligned.m16n8k16.row.col.f32.bf16.bf16.f32 "
        "{%0,%1,%2,%3}, {%4,%5,%6,%7}, {%8,%9}, {%0,%1,%2,%3};"
        : "+f"(c[0]), "+f"(c[1]), "+f"(c[2]), "+f"(c[3])
        : "r"(a[0]), "r"(a[1]), "r"(a[2]), "r"(a[3]), "r"(b[0]), "r"(b[1]));
}
__device__ __forceinline__ void ldmx4(uint32_t r[4], uint32_t addr) {
    asm volatile("ldmatrix.sync.aligned.m8n8.x4.shared.b16 {%0,%1,%2,%3}, [%4];"
                 : "=r"(r[0]), "=r"(r[1]), "=r"(r[2]), "=r"(r[3]) : "r"(addr));
}
__device__ __forceinline__ void ldmx2(uint32_t r[2], uint32_t addr) {
    asm volatile("ldmatrix.sync.aligned.m8n8.x2.shared.b16 {%0,%1}, [%2];"
                 : "=r"(r[0]), "=r"(r[1]) : "r"(addr));
}
__device__ __forceinline__ uint32_t smaddr(const void* p) {
    return (uint32_t)__cvta_generic_to_shared(p);
}

namespace {
constexpr int KPS = 36;   // bf16x2-pair stride (padded; conflict-free)
constexpr int BSTEP = 16 * KPS * 4;
}

// ============================================================================
// Projection GEMM (bf16 3-term): Y[M,512] = X @ W^T + bias  (unchanged R11)
// ============================================================================
namespace {
constexpr int GM_XHI = 0;
constexpr int GM_XLO = 128 * KPS;
constexpr int GM_WHI = 2 * 128 * KPS;
constexpr int GM_WLO = 3 * 128 * KPS;
constexpr int SMEM_GEMM = 4 * 128 * KPS * 4;     // 73,728 bytes
}

__global__ void __launch_bounds__(256, 2) gemm_mma(
    const float* __restrict__ X, const float* __restrict__ W,
    const float* __restrict__ bias, float* __restrict__ Y)
{
    extern __shared__ uint32_t smu[];
    uint32_t* Xhi = smu + GM_XHI;
    uint32_t* Xlo = smu + GM_XLO;
    uint32_t* Whi = smu + GM_WHI;
    uint32_t* Wlo = smu + GM_WLO;

    const int t = threadIdx.x, lane = t & 31, wid = t >> 5;
    const int g = lane >> 2, tig = lane & 3;
    const int wm = wid & 1, wn = wid >> 1;
    const int m0 = blockIdx.y * 128, n0 = blockIdx.x * 128;

    const int am = lane >> 3, arm = lane & 7;
    const int bmat = (lane >> 3) & 1, brm = lane & 7;
    uint32_t aHi[4], aLo[4], bHi[4], bLo[4];
#pragma unroll
    for (int i = 0; i < 4; i++) {
        const int row = wm * 64 + i * 16 + (am & 1) * 8 + arm;
        const uint32_t off = (uint32_t)(row * KPS + (am >> 1) * 4) * 4u;
        aHi[i] = smaddr(Xhi) + off;
        aLo[i] = smaddr(Xlo) + off;
    }
#pragma unroll
    for (int j = 0; j < 4; j++) {
        const int row = wn * 32 + j * 8 + brm;
        const uint32_t off = (uint32_t)(row * KPS + bmat * 4) * 4u;
        bHi[j] = smaddr(Whi) + off;
        bLo[j] = smaddr(Wlo) + off;
    }

    float acc[4][4][4] = {};

    for (int kc = 0; kc < 512; kc += 64) {
#pragma unroll
        for (int i = t; i < 2048; i += 256) {
            const int row = i >> 4, c4 = (i & 15) * 4, p = c4 >> 1;
            float4 xv = *reinterpret_cast<const float4*>(&X[(size_t)(m0 + row) * 512 + kc + c4]);
            float4 wv = *reinterpret_cast<const float4*>(&W[(size_t)(n0 + row) * 512 + kc + c4]);
            uint2 h, l;
            split_bf16x2(xv.x, xv.y, h.x, l.x);
            split_bf16x2(xv.z, xv.w, h.y, l.y);
            *reinterpret_cast<uint2*>(&Xhi[row * KPS + p]) = h;
            *reinterpret_cast<uint2*>(&Xlo[row * KPS + p]) = l;
            split_bf16x2(wv.x, wv.y, h.x, l.x);
            split_bf16x2(wv.z, wv.w, h.y, l.y);
            *reinterpret_cast<uint2*>(&Whi[row * KPS + p]) = h;
            *reinterpret_cast<uint2*>(&Wlo[row * KPS + p]) = l;
        }
        __syncthreads();

#pragma unroll
        for (int ks = 0; ks < 4; ks++) {
            const uint32_t ko = ks * 32u;
            uint32_t ahi[4][4], alo[4][4];
#pragma unroll
            for (int i = 0; i < 4; i++) {
                ldmx4(ahi[i], aHi[i] + ko);
                ldmx4(alo[i], aLo[i] + ko);
            }
#pragma unroll
            for (int j = 0; j < 4; j++) {
                uint32_t bhi[2], blo[2];
                ldmx2(bhi, bHi[j] + ko);
                ldmx2(blo, bLo[j] + ko);
#pragma unroll
                for (int i = 0; i < 4; i++) {
                    mma_bf16(acc[i][j], ahi[i], bhi);
                    mma_bf16(acc[i][j], alo[i], bhi);
                    mma_bf16(acc[i][j], ahi[i], blo);
                }
            }
        }
        __syncthreads();
    }

#pragma unroll
    for (int i = 0; i < 4; i++) {
        const int row0 = m0 + wm * 64 + i * 16 + g;
#pragma unroll
        for (int j = 0; j < 4; j++) {
            const int col = n0 + wn * 32 + j * 8 + 2 * tig;
            const float b0 = __ldg(bias + col), b1 = __ldg(bias + col + 1);
            float2 o;
            o.x = acc[i][j][0] + b0; o.y = acc[i][j][1] + b1;
            *reinterpret_cast<float2*>(&Y[(size_t)row0 * 512 + col]) = o;
            o.x = acc[i][j][2] + b0; o.y = acc[i][j][3] + b1;
            *reinterpret_cast<float2*>(&Y[(size_t)(row0 + 8) * 512 + col]) = o;
        }
    }
}

// ============================================================================
// stats_mma: 128-thread CTA (4 warps), 64-row q-strip, M-only warp layout.
// Online (max, sumexp) -> rowM, rowInv. Each row owned by ONE warp.
// ============================================================================
namespace {
constexpr int S2_QHI = 0;
constexpr int S2_QLO = 64 * KPS;
constexpr int S2_KHI = 2 * 64 * KPS;
constexpr int S2_KLO = 3 * 64 * KPS;
constexpr int SMEM_STATS = 4 * 64 * KPS * 4;      // 36,864 bytes
}

__global__ void __launch_bounds__(128, 4) stats_mma(
    const float* __restrict__ Q, const float* __restrict__ K,
    const int* __restrict__ mask, const float* __restrict__ is_org,
    const float* __restrict__ Worg, const float* __restrict__ borg,
    float* __restrict__ rowM, float* __restrict__ rowInv)
{
    extern __shared__ uint32_t smu[];
    uint32_t* Qhi = smu + S2_QHI;
    uint32_t* Qlo = smu + S2_QLO;
    uint32_t* Khi = smu + S2_KHI;
    uint32_t* Klo = smu + S2_KLO;

    const int t = threadIdx.x, lane = t & 31, wid = t >> 5;   // wid 0..3
    const int g = lane >> 2, tig = lane & 3;
    const int bh = blockIdx.y, b = bh >> 3, h = bh & 7;
    const int q0 = blockIdx.x * 64;

    const float* Qg = Q + ((size_t)(b * S + q0)) * D + h * DK;
    const float* Kg = K + ((size_t)(b * S)) * D + h * DK;

    // Q strip (64 rows) split
#pragma unroll
    for (int i = t; i < 1024; i += 128) {
        const int row = i >> 4, c4 = (i & 15) * 4, p = c4 >> 1;
        float4 qv = *reinterpret_cast<const float4*>(Qg + (size_t)row * D + c4);
        uint2 h2, l2;
        split_bf16x2(qv.x, qv.y, h2.x, l2.x);
        split_bf16x2(qv.z, qv.w, h2.y, l2.y);
        *reinterpret_cast<uint2*>(&Qhi[row * KPS + p]) = h2;
        *reinterpret_cast<uint2*>(&Qlo[row * KPS + p]) = l2;
    }

    // A (Q) ldmatrix base: one 16-row m-tile per warp
    const int am = lane >> 3, arm = lane & 7;
    uint32_t aQhi, aQlo;
    {
        const int row = wid * 16 + (am & 1) * 8 + arm;
        const uint32_t off = (uint32_t)(row * KPS + (am >> 1) * 4) * 4u;
        aQhi = smaddr(Qhi) + off;
        aQlo = smaddr(Qlo) + off;
    }
    // B x4 base spanning two 8-row n-tiles
    uint32_t bKhi, bKlo;
    {
        const int brow = ((lane >> 4) & 1) * 8 + (lane & 7);
        const int bkp  = ((lane >> 3) & 1) * 4;
        const uint32_t off = (uint32_t)(brow * KPS + bkp) * 4u;
        bKhi = smaddr(Khi) + off;
        bKlo = smaddr(Klo) + off;
    }

    const float worg = __ldg(Worg + h), bog = __ldg(borg + h);
    const int r0 = wid * 16 + g;
    const float og0 = __ldg(is_org + b * S + q0 + r0) * worg + bog;
    const float og1 = __ldg(is_org + b * S + q0 + r0 + 8) * worg + bog;

    float rm0 = -1e30f, rs0 = 0.0f, rm1 = -1e30f, rs1 = 0.0f;

    for (int kt = 0; kt < 32; kt++) {
        // K tile (64 rows) split
#pragma unroll
        for (int i = t; i < 1024; i += 128) {
            const int row = i >> 4, c4 = (i & 15) * 4, p = c4 >> 1;
            float4 kv = *reinterpret_cast<const float4*>(
                Kg + (size_t)(kt * 64 + row) * D + c4);
            uint2 h2, l2;
            split_bf16x2(kv.x, kv.y, h2.x, l2.x);
            split_bf16x2(kv.z, kv.w, h2.y, l2.y);
            *reinterpret_cast<uint2*>(&Khi[row * KPS + p]) = h2;
            *reinterpret_cast<uint2*>(&Klo[row * KPS + p]) = l2;
        }
        __syncthreads();

        // QK for this warp's 16 rows x 64 cols
        float acc[8][4] = {};
#pragma unroll
        for (int ks = 0; ks < 4; ks++) {
            const uint32_t ko = ks * 32u;
            uint32_t ah[4], al[4];
            ldmx4(ah, aQhi + ko);
            ldmx4(al, aQlo + ko);
#pragma unroll
            for (int jp = 0; jp < 4; jp++) {
                uint32_t bhv[4], blv[4];
                ldmx4(bhv, bKhi + jp * BSTEP + ko);
                ldmx4(blv, bKlo + jp * BSTEP + ko);
                mma_bf16(acc[2 * jp],     ah, bhv);
                mma_bf16(acc[2 * jp],     al, bhv);
                mma_bf16(acc[2 * jp],     ah, blv);
                mma_bf16(acc[2 * jp + 1], ah, bhv + 2);
                mma_bf16(acc[2 * jp + 1], al, bhv + 2);
                mma_bf16(acc[2 * jp + 1], ah, blv + 2);
            }
        }
        __syncthreads();   // K smem free for next copy; epilogue is reg-only

        // Logits + mask
#pragma unroll
        for (int j = 0; j < 8; j++) {
            const int2 mj = *reinterpret_cast<const int2*>(
                mask + b * S + kt * 64 + j * 8 + 2 * tig);
            float v;
            v = acc[j][0] * 0.125f + og0; acc[j][0] = mj.x ? v : -1e9f;
            v = acc[j][1] * 0.125f + og0; acc[j][1] = mj.y ? v : -1e9f;
            v = acc[j][2] * 0.125f + og1; acc[j][2] = mj.x ? v : -1e9f;
            v = acc[j][3] * 0.125f + og1; acc[j][3] = mj.y ? v : -1e9f;
        }

        // Online stats for rows r0 and r0+8
        {
            float mt0 = -1e30f, mt1 = -1e30f;
#pragma unroll
            for (int j = 0; j < 8; j++) {
                mt0 = fmaxf(mt0, fmaxf(acc[j][0], acc[j][1]));
                mt1 = fmaxf(mt1, fmaxf(acc[j][2], acc[j][3]));
            }
            mt0 = fmaxf(mt0, __shfl_xor_sync(0xffffffffu, mt0, 1));
            mt0 = fmaxf(mt0, __shfl_xor_sync(0xffffffffu, mt0, 2));
            mt1 = fmaxf(mt1, __shfl_xor_sync(0xffffffffu, mt1, 1));
            mt1 = fmaxf(mt1, __shfl_xor_sync(0xffffffffu, mt1, 2));
            const float mn0 = fmaxf(rm0, mt0);
            const float mn1 = fmaxf(rm1, mt1);
            float s0 = 0.0f, s1 = 0.0f;
#pragma unroll
            for (int j = 0; j < 8; j++) {
                s0 += __expf(acc[j][0] - mn0) + __expf(acc[j][1] - mn0);
                s1 += __expf(acc[j][2] - mn1) + __expf(acc[j][3] - mn1);
            }
            s0 += __shfl_xor_sync(0xffffffffu, s0, 1);
            s0 += __shfl_xor_sync(0xffffffffu, s0, 2);
            s1 += __shfl_xor_sync(0xffffffffu, s1, 1);
            s1 += __shfl_xor_sync(0xffffffffu, s1, 2);
            rs0 = rs0 * __expf(rm0 - mn0) + s0; rm0 = mn0;
            rs1 = rs1 * __expf(rm1 - mn1) + s1; rm1 = mn1;
        }
    }

    if (tig == 0) {
        rowM[(size_t)bh * S + q0 + r0] = rm0;
        rowInv[(size_t)bh * S + q0 + r0] = 1.0f / rs0;
        rowM[(size_t)bh * S + q0 + r0 + 8] = rm1;
        rowInv[(size_t)bh * S + q0 + r0 + 8] = 1.0f / rs1;
    }
}

// ============================================================================
// av_fused: 128-thread CTA (4 warps), 64-row q-strip, FA2 register reuse.
// ============================================================================
namespace {
constexpr int AF_QHI = 0;
constexpr int AF_QLO = 64 * KPS;
constexpr int AF_KHI = 2 * 64 * KPS;
constexpr int AF_KLO = 3 * 64 * KPS;
constexpr int AF_VHI = 4 * 64 * KPS;
constexpr int AF_VLO = 5 * 64 * KPS;
constexpr int AF_RM  = 6 * 64 * KPS;
constexpr int AF_RI  = AF_RM + 64;
constexpr int SMEM_AF = (AF_RI + 64) * 4;     // 55,808 bytes
}

__global__ void __launch_bounds__(128, 4) av_fused(
    const float* __restrict__ Q, const float* __restrict__ K,
    const float* __restrict__ V,
    const int* __restrict__ mask, const float* __restrict__ is_org,
    const float* __restrict__ Worg, const float* __restrict__ borg,
    const float* __restrict__ rowM, const float* __restrict__ rowInv,
    float* __restrict__ att, float* __restrict__ C)
{
    extern __shared__ uint32_t smu[];
    uint32_t* Qhi = smu + AF_QHI;
    uint32_t* Qlo = smu + AF_QLO;
    uint32_t* Khi = smu + AF_KHI;
    uint32_t* Klo = smu + AF_KLO;
    uint32_t* Vhi = smu + AF_VHI;
    uint32_t* Vlo = smu + AF_VLO;
    float*    Rm  = reinterpret_cast<float*>(smu + AF_RM);
    float*    Ri  = reinterpret_cast<float*>(smu + AF_RI);

    const int t = threadIdx.x, lane = t & 31, wid = t >> 5;   // wid 0..3
    const int g = lane >> 2, tig = lane & 3;
    const int bh = blockIdx.y, b = bh >> 3, h = bh & 7;
    const int q0 = blockIdx.x * 64;

    const float* Qg = Q + ((size_t)(b * S + q0)) * D + h * DK;
    const float* Kg = K + ((size_t)(b * S)) * D + h * DK;
    const float* Vg = V + ((size_t)(b * S)) * D + h * DK;

    if (t < 64) {
        Rm[t] = rowM[(size_t)bh * S + q0 + t];
        Ri[t] = rowInv[(size_t)bh * S + q0 + t];
    }
#pragma unroll
    for (int i = t; i < 1024; i += 128) {
        const int row = i >> 4, c4 = (i & 15) * 4, p = c4 >> 1;
        float4 qv = *reinterpret_cast<const float4*>(Qg + (size_t)row * D + c4);
        uint2 h2, l2;
        split_bf16x2(qv.x, qv.y, h2.x, l2.x);
        split_bf16x2(qv.z, qv.w, h2.y, l2.y);
        *reinterpret_cast<uint2*>(&Qhi[row * KPS + p]) = h2;
        *reinterpret_cast<uint2*>(&Qlo[row * KPS + p]) = l2;
    }

    const int am = lane >> 3, arm = lane & 7;
    uint32_t aQhi, aQlo;
    {
        const int row = wid * 16 + (am & 1) * 8 + arm;
        const uint32_t off = (uint32_t)(row * KPS + (am >> 1) * 4) * 4u;
        aQhi = smaddr(Qhi) + off;
        aQlo = smaddr(Qlo) + off;
    }
    uint32_t bKhi, bKlo, bVhi, bVlo;
    {
        const int brow = ((lane >> 4) & 1) * 8 + (lane & 7);
        const int bkp  = ((lane >> 3) & 1) * 4;
        const uint32_t off = (uint32_t)(brow * KPS + bkp) * 4u;
        bKhi = smaddr(Khi) + off; bKlo = smaddr(Klo) + off;
        bVhi = smaddr(Vhi) + off; bVlo = smaddr(Vlo) + off;
    }

    const float worg = __ldg(Worg + h), bog = __ldg(borg + h);
    const int r0 = wid * 16 + g;
    const float og0 = __ldg(is_org + b * S + q0 + r0) * worg + bog;
    const float og1 = __ldg(is_org + b * S + q0 + r0 + 8) * worg + bog;

    __syncthreads();
    const float M0 = Rm[r0], I0 = Ri[r0];
    const float M1 = Rm[r0 + 8], I1 = Ri[r0 + 8];

    float accAV[8][4] = {};

    for (int kt = 0; kt < 32; kt++) {
        // K tile split
#pragma unroll
        for (int i = t; i < 1024; i += 128) {
            const int row = i >> 4, c4 = (i & 15) * 4, p = c4 >> 1;
            float4 kv = *reinterpret_cast<const float4*>(
                Kg + (size_t)(kt * 64 + row) * D + c4);
            uint2 h2, l2;
            split_bf16x2(kv.x, kv.y, h2.x, l2.x);
            split_bf16x2(kv.z, kv.w, h2.y, l2.y);
            *reinterpret_cast<uint2*>(&Khi[row * KPS + p]) = h2;
            *reinterpret_cast<uint2*>(&Klo[row * KPS + p]) = l2;
        }
        // V tile split + transpose ([d][kp])
#pragma unroll
        for (int i = t; i < 512; i += 128) {
            const int dg = i & 15, kp = i >> 4;
            const float* vp = Vg + (size_t)(kt * 64 + 2 * kp) * D + dg * 4;
            float4 va = *reinterpret_cast<const float4*>(vp);
            float4 vb = *reinterpret_cast<const float4*>(vp + D);
            uint32_t hi, lo;
            split_bf16x2(va.x, vb.x, hi, lo);
            Vhi[(dg * 4 + 0) * KPS + kp] = hi; Vlo[(dg * 4 + 0) * KPS + kp] = lo;
            split_bf16x2(va.y, vb.y, hi, lo);
            Vhi[(dg * 4 + 1) * KPS + kp] = hi; Vlo[(dg * 4 + 1) * KPS + kp] = lo;
            split_bf16x2(va.z, vb.z, hi, lo);
            Vhi[(dg * 4 + 2) * KPS + kp] = hi; Vlo[(dg * 4 + 2) * KPS + kp] = lo;
            split_bf16x2(va.w, vb.w, hi, lo);
            Vhi[(dg * 4 + 3) * KPS + kp] = hi; Vlo[(dg * 4 + 3) * KPS + kp] = lo;
        }
        __syncthreads();

        // QK
        float acc[8][4] = {};
#pragma unroll
        for (int ks = 0; ks < 4; ks++) {
            const uint32_t ko = ks * 32u;
            uint32_t ah[4], al[4];
            ldmx4(ah, aQhi + ko);
            ldmx4(al, aQlo + ko);
#pragma unroll
            for (int jp = 0; jp < 4; jp++) {
                uint32_t bhv[4], blv[4];
                ldmx4(bhv, bKhi + jp * BSTEP + ko);
                ldmx4(blv, bKlo + jp * BSTEP + ko);
                mma_bf16(acc[2 * jp],     ah, bhv);
                mma_bf16(acc[2 * jp],     al, bhv);
                mma_bf16(acc[2 * jp],     ah, blv);
                mma_bf16(acc[2 * jp + 1], ah, bhv + 2);
                mma_bf16(acc[2 * jp + 1], al, bhv + 2);
                mma_bf16(acc[2 * jp + 1], ah, blv + 2);
            }
        }

        // Softmax epilogue: p = exp(x - M) * Inv; write p to att; keep in acc
        float* arow0 = &att[((size_t)bh * S + q0 + r0) * S + kt * 64 + 2 * tig];
        float* arow1 = arow0 + 8 * S;
#pragma unroll
        for (int j = 0; j < 8; j++) {
            const int2 mj = *reinterpret_cast<const int2*>(
                mask + b * S + kt * 64 + j * 8 + 2 * tig);
            float x0 = acc[j][0] * 0.125f + og0;
            float x1 = acc[j][1] * 0.125f + og0;
            float x2 = acc[j][2] * 0.125f + og1;
            float x3 = acc[j][3] * 0.125f + og1;
            x0 = mj.x ? x0 : -1e9f;
            x1 = mj.y ? x1 : -1e9f;
            x2 = mj.x ? x2 : -1e9f;
            x3 = mj.y ? x3 : -1e9f;
            const float p0 = __expf(x0 - M0) * I0;
            const float p1 = __expf(x1 - M0) * I0;
            const float p2 = __expf(x2 - M1) * I1;
            const float p3 = __expf(x3 - M1) * I1;
            float2 o;
            o.x = p0; o.y = p1;
            *reinterpret_cast<float2*>(arow0 + j * 8) = o;
            o.x = p2; o.y = p3;
            *reinterpret_cast<float2*>(arow1 + j * 8) = o;
            acc[j][0] = p0; acc[j][1] = p1; acc[j][2] = p2; acc[j][3] = p3;
        }

        // PV: A-frags packed directly from acc
#pragma unroll
        for (int jj = 0; jj < 4; jj++) {
            uint32_t ph[4], pl[4];
            split_bf16x2(acc[2 * jj][0],     acc[2 * jj][1],     ph[0], pl[0]);
            split_bf16x2(acc[2 * jj][2],     acc[2 * jj][3],     ph[1], pl[1]);
            split_bf16x2(acc[2 * jj + 1][0], acc[2 * jj + 1][1], ph[2], pl[2]);
            split_bf16x2(acc[2 * jj + 1][2], acc[2 * jj + 1][3], ph[3], pl[3]);
            const uint32_t ko = jj * 32u;
#pragma unroll
            for (int dp = 0; dp < 4; dp++) {
                uint32_t vh[4], vl[4];
                ldmx4(vh, bVhi + dp * BSTEP + ko);
                ldmx4(vl, bVlo + dp * BSTEP + ko);
                mma_bf16(accAV[2 * dp],     ph, vh);
                mma_bf16(accAV[2 * dp],     pl, vh);
                mma_bf16(accAV[2 * dp],     ph, vl);
                mma_bf16(accAV[2 * dp + 1], ph, vh + 2);
                mma_bf16(accAV[2 * dp + 1], pl, vh + 2);
                mma_bf16(accAV[2 * dp + 1], ph, vl + 2);
            }
        }
        __syncthreads();
    }

    // Store context C
#pragma unroll
    for (int dj = 0; dj < 8; dj++) {
        const int col = h * DK + dj * 8 + 2 * tig;
        float2 o;
        o.x = accAV[dj][0]; o.y = accAV[dj][1];
        *reinterpret_cast<float2*>(&C[(size_t)(b * S + q0 + r0) * D + col]) = o;
        o.x = accAV[dj][2]; o.y = accAV[dj][3];
        *reinterpret_cast<float2*>(&C[(size_t)(b * S + q0 + r0 + 8) * D + col]) = o;
    }
}

// ---------------------------------------------------------------------------
extern "C" void kernel_launch(void* const* d_in, const int* in_sizes, int n_in,
                              void* d_out, int out_size)
{
    const float* query = (const float*)d_in[0];
    const float* key   = (const float*)d_in[1];
    const float* value = (const float*)d_in[2];
    const int*   mask  = (const int*)d_in[3];
    const float* isog  = (const float*)d_in[4];
    const float* Wq    = (const float*)d_in[5];
    const float* bq    = (const float*)d_in[6];
    const float* Wk    = (const float*)d_in[7];
    const float* bk    = (const float*)d_in[8];
    const float* Wv    = (const float*)d_in[9];
    const float* bv    = (const float*)d_in[10];
    const float* Wo    = (const float*)d_in[11];
    const float* bo    = (const float*)d_in[12];
    const float* Worg  = (const float*)d_in[13];
    const float* borg  = (const float*)d_in[14];

    float* out = (float*)d_out;

    float *qbuf, *kbuf, *vbuf, *cbuf, *rowM, *rowInv;
    cudaGetSymbolAddress((void**)&qbuf, g_Q);
    cudaGetSymbolAddress((void**)&kbuf, g_K);
    cudaGetSymbolAddress((void**)&vbuf, g_V);
    cudaGetSymbolAddress((void**)&cbuf, g_C);
    cudaGetSymbolAddress((void**)&rowM, g_rowM);
    cudaGetSymbolAddress((void**)&rowInv, g_rowInv);

    const long long OUT_MAIN = (long long)B * S * D;
    const long long ATT_SZ   = (long long)B * H * S * S;
    float* att;
    if ((long long)out_size >= OUT_MAIN + ATT_SZ) {
        att = out + OUT_MAIN;
    } else {
        cudaGetSymbolAddress((void**)&att, g_att);
    }

    static bool attr_done = false;
    if (!attr_done) {
        cudaFuncSetAttribute(gemm_mma,  cudaFuncAttributeMaxDynamicSharedMemorySize, SMEM_GEMM);
        cudaFuncSetAttribute(stats_mma, cudaFuncAttributeMaxDynamicSharedMemorySize, SMEM_STATS);
        cudaFuncSetAttribute(av_fused,  cudaFuncAttributeMaxDynamicSharedMemorySize, SMEM_AF);
        attr_done = true;
    }

    dim3 gg(4, 64);
    gemm_mma<<<gg, 256, SMEM_GEMM>>>(query, Wq, bq, qbuf);
    gemm_mma<<<gg, 256, SMEM_GEMM>>>(key,   Wk, bk, kbuf);
    gemm_mma<<<gg, 256, SMEM_GEMM>>>(value, Wv, bv, vbuf);

    dim3 gf(S / 64, B * H);
    stats_mma<<<gf, 128, SMEM_STATS>>>(qbuf, kbuf, mask, isog, Worg, borg, rowM, rowInv);

    av_fused<<<gf, 128, SMEM_AF>>>(qbuf, kbuf, vbuf, mask, isog, Worg, borg,
                                   rowM, rowInv, att, cbuf);

    gemm_mma<<<gg, 256, SMEM_GEMM>>>(cbuf, Wo, bo, out);
}

// round 15
// speedup vs baseline: 1.0661x; 1.0335x over previous
#include <cuda_runtime.h>
#include <cstdint>

namespace {
constexpr int B = 4, S = 2048, D = 512, H = 8, DK = 64;
}

// Scratch (allocation-free rule: __device__ globals)
__device__ float g_Q[(size_t)B * S * D];
__device__ float g_K[(size_t)B * S * D];
__device__ float g_V[(size_t)B * S * D];
__device__ float g_C[(size_t)B * S * D];
__device__ float g_att[(size_t)B * H * S * S];
__device__ float g_rowM[(size_t)B * H * S];
__device__ float g_rowInv[(size_t)B * H * S];

// ============================================================================
// bf16 split, MMA, ldmatrix helpers (portable PTX — works on compute_103)
// ============================================================================
__device__ __forceinline__ void split_bf16x2(float x0, float x1, uint32_t& hi, uint32_t& lo) {
    asm("cvt.rn.bf16x2.f32 %0, %1, %2;" : "=r"(hi) : "f"(x1), "f"(x0));
    const float h0 = __uint_as_float(hi << 16);
    const float h1 = __uint_as_float(hi & 0xFFFF0000u);
    asm("cvt.rn.bf16x2.f32 %0, %1, %2;" : "=r"(lo) : "f"(x1 - h1), "f"(x0 - h0));
}
__device__ __forceinline__ void mma_bf16(float c[4], const uint32_t a[4], const uint32_t b[2]) {
    asm volatile(
        "mma.sync.aligned.m16n8k16.row.col.f32.bf16.bf16.f32 "
        "{%0,%1,%2,%3}, {%4,%5,%6,%7}, {%8,%9}, {%0,%1,%2,%3};"
        : "+f"(c[0]), "+f"(c[1]), "+f"(c[2]), "+f"(c[3])
        : "r"(a[0]), "r"(a[1]), "r"(a[2]), "r"(a[3]), "r"(b[0]), "r"(b[1]));
}
__device__ __forceinline__ void ldmx4(uint32_t r[4], uint32_t addr) {
    asm volatile("ldmatrix.sync.aligned.m8n8.x4.shared.b16 {%0,%1,%2,%3}, [%4];"
                 : "=r"(r[0]), "=r"(r[1]), "=r"(r[2]), "=r"(r[3]) : "r"(addr));
}
__device__ __forceinline__ void ldmx2(uint32_t r[2], uint32_t addr) {
    asm volatile("ldmatrix.sync.aligned.m8n8.x2.shared.b16 {%0,%1}, [%2];"
                 : "=r"(r[0]), "=r"(r[1]) : "r"(addr));
}
__device__ __forceinline__ uint32_t smaddr(const void* p) {
    return (uint32_t)__cvta_generic_to_shared(p);
}

namespace {
constexpr int KPS = 36;   // bf16x2-pair stride (padded; conflict-free)
constexpr int BSTEP = 16 * KPS * 4;
}

// ============================================================================
// Projection GEMM (bf16 3-term): Y[M,512] = X @ W^T + bias
// ============================================================================
namespace {
constexpr int GM_XHI = 0;
constexpr int GM_XLO = 128 * KPS;
constexpr int GM_WHI = 2 * 128 * KPS;
constexpr int GM_WLO = 3 * 128 * KPS;
constexpr int SMEM_GEMM = 4 * 128 * KPS * 4;     // 73,728 bytes
}

__global__ void __launch_bounds__(256, 2) gemm_mma(
    const float* __restrict__ X, const float* __restrict__ W,
    const float* __restrict__ bias, float* __restrict__ Y)
{
    extern __shared__ uint32_t smu[];
    uint32_t* Xhi = smu + GM_XHI;
    uint32_t* Xlo = smu + GM_XLO;
    uint32_t* Whi = smu + GM_WHI;
    uint32_t* Wlo = smu + GM_WLO;

    const int t = threadIdx.x, lane = t & 31, wid = t >> 5;
    const int g = lane >> 2, tig = lane & 3;
    const int wm = wid & 1, wn = wid >> 1;
    const int m0 = blockIdx.y * 128, n0 = blockIdx.x * 128;

    const int am = lane >> 3, arm = lane & 7;
    const int bmat = (lane >> 3) & 1, brm = lane & 7;
    uint32_t aHi[4], aLo[4], bHi[4], bLo[4];
#pragma unroll
    for (int i = 0; i < 4; i++) {
        const int row = wm * 64 + i * 16 + (am & 1) * 8 + arm;
        const uint32_t off = (uint32_t)(row * KPS + (am >> 1) * 4) * 4u;
        aHi[i] = smaddr(Xhi) + off;
        aLo[i] = smaddr(Xlo) + off;
    }
#pragma unroll
    for (int j = 0; j < 4; j++) {
        const int row = wn * 32 + j * 8 + brm;
        const uint32_t off = (uint32_t)(row * KPS + bmat * 4) * 4u;
        bHi[j] = smaddr(Whi) + off;
        bLo[j] = smaddr(Wlo) + off;
    }

    float acc[4][4][4] = {};

    for (int kc = 0; kc < 512; kc += 64) {
#pragma unroll
        for (int i = t; i < 2048; i += 256) {
            const int row = i >> 4, c4 = (i & 15) * 4, p = c4 >> 1;
            float4 xv = *reinterpret_cast<const float4*>(&X[(size_t)(m0 + row) * 512 + kc + c4]);
            float4 wv = *reinterpret_cast<const float4*>(&W[(size_t)(n0 + row) * 512 + kc + c4]);
            uint2 h, l;
            split_bf16x2(xv.x, xv.y, h.x, l.x);
            split_bf16x2(xv.z, xv.w, h.y, l.y);
            *reinterpret_cast<uint2*>(&Xhi[row * KPS + p]) = h;
            *reinterpret_cast<uint2*>(&Xlo[row * KPS + p]) = l;
            split_bf16x2(wv.x, wv.y, h.x, l.x);
            split_bf16x2(wv.z, wv.w, h.y, l.y);
            *reinterpret_cast<uint2*>(&Whi[row * KPS + p]) = h;
            *reinterpret_cast<uint2*>(&Wlo[row * KPS + p]) = l;
        }
        __syncthreads();

#pragma unroll
        for (int ks = 0; ks < 4; ks++) {
            const uint32_t ko = ks * 32u;
            uint32_t ahi[4][4], alo[4][4];
#pragma unroll
            for (int i = 0; i < 4; i++) {
                ldmx4(ahi[i], aHi[i] + ko);
                ldmx4(alo[i], aLo[i] + ko);
            }
#pragma unroll
            for (int j = 0; j < 4; j++) {
                uint32_t bhi[2], blo[2];
                ldmx2(bhi, bHi[j] + ko);
                ldmx2(blo, bLo[j] + ko);
#pragma unroll
                for (int i = 0; i < 4; i++) {
                    mma_bf16(acc[i][j], ahi[i], bhi);
                    mma_bf16(acc[i][j], alo[i], bhi);
                    mma_bf16(acc[i][j], ahi[i], blo);
                }
            }
        }
        __syncthreads();
    }

#pragma unroll
    for (int i = 0; i < 4; i++) {
        const int row0 = m0 + wm * 64 + i * 16 + g;
#pragma unroll
        for (int j = 0; j < 4; j++) {
            const int col = n0 + wn * 32 + j * 8 + 2 * tig;
            const float b0 = __ldg(bias + col), b1 = __ldg(bias + col + 1);
            float2 o;
            o.x = acc[i][j][0] + b0; o.y = acc[i][j][1] + b1;
            *reinterpret_cast<float2*>(&Y[(size_t)row0 * 512 + col]) = o;
            o.x = acc[i][j][2] + b0; o.y = acc[i][j][3] + b1;
            *reinterpret_cast<float2*>(&Y[(size_t)(row0 + 8) * 512 + col]) = o;
        }
    }
}

// ============================================================================
// stats_mma: 128-thread CTA (4 warps), 64-row q-strip, M-only warp layout.
// (R14 shape — measured best for stats)
// ============================================================================
namespace {
constexpr int S2_QHI = 0;
constexpr int S2_QLO = 64 * KPS;
constexpr int S2_KHI = 2 * 64 * KPS;
constexpr int S2_KLO = 3 * 64 * KPS;
constexpr int SMEM_STATS = 4 * 64 * KPS * 4;      // 36,864 bytes
}

__global__ void __launch_bounds__(128, 4) stats_mma(
    const float* __restrict__ Q, const float* __restrict__ K,
    const int* __restrict__ mask, const float* __restrict__ is_org,
    const float* __restrict__ Worg, const float* __restrict__ borg,
    float* __restrict__ rowM, float* __restrict__ rowInv)
{
    extern __shared__ uint32_t smu[];
    uint32_t* Qhi = smu + S2_QHI;
    uint32_t* Qlo = smu + S2_QLO;
    uint32_t* Khi = smu + S2_KHI;
    uint32_t* Klo = smu + S2_KLO;

    const int t = threadIdx.x, lane = t & 31, wid = t >> 5;   // wid 0..3
    const int g = lane >> 2, tig = lane & 3;
    const int bh = blockIdx.y, b = bh >> 3, h = bh & 7;
    const int q0 = blockIdx.x * 64;

    const float* Qg = Q + ((size_t)(b * S + q0)) * D + h * DK;
    const float* Kg = K + ((size_t)(b * S)) * D + h * DK;

#pragma unroll
    for (int i = t; i < 1024; i += 128) {
        const int row = i >> 4, c4 = (i & 15) * 4, p = c4 >> 1;
        float4 qv = *reinterpret_cast<const float4*>(Qg + (size_t)row * D + c4);
        uint2 h2, l2;
        split_bf16x2(qv.x, qv.y, h2.x, l2.x);
        split_bf16x2(qv.z, qv.w, h2.y, l2.y);
        *reinterpret_cast<uint2*>(&Qhi[row * KPS + p]) = h2;
        *reinterpret_cast<uint2*>(&Qlo[row * KPS + p]) = l2;
    }

    const int am = lane >> 3, arm = lane & 7;
    uint32_t aQhi, aQlo;
    {
        const int row = wid * 16 + (am & 1) * 8 + arm;
        const uint32_t off = (uint32_t)(row * KPS + (am >> 1) * 4) * 4u;
        aQhi = smaddr(Qhi) + off;
        aQlo = smaddr(Qlo) + off;
    }
    uint32_t bKhi, bKlo;
    {
        const int brow = ((lane >> 4) & 1) * 8 + (lane & 7);
        const int bkp  = ((lane >> 3) & 1) * 4;
        const uint32_t off = (uint32_t)(brow * KPS + bkp) * 4u;
        bKhi = smaddr(Khi) + off;
        bKlo = smaddr(Klo) + off;
    }

    const float worg = __ldg(Worg + h), bog = __ldg(borg + h);
    const int r0 = wid * 16 + g;
    const float og0 = __ldg(is_org + b * S + q0 + r0) * worg + bog;
    const float og1 = __ldg(is_org + b * S + q0 + r0 + 8) * worg + bog;

    float rm0 = -1e30f, rs0 = 0.0f, rm1 = -1e30f, rs1 = 0.0f;

    for (int kt = 0; kt < 32; kt++) {
#pragma unroll
        for (int i = t; i < 1024; i += 128) {
            const int row = i >> 4, c4 = (i & 15) * 4, p = c4 >> 1;
            float4 kv = *reinterpret_cast<const float4*>(
                Kg + (size_t)(kt * 64 + row) * D + c4);
            uint2 h2, l2;
            split_bf16x2(kv.x, kv.y, h2.x, l2.x);
            split_bf16x2(kv.z, kv.w, h2.y, l2.y);
            *reinterpret_cast<uint2*>(&Khi[row * KPS + p]) = h2;
            *reinterpret_cast<uint2*>(&Klo[row * KPS + p]) = l2;
        }
        __syncthreads();

        float acc[8][4] = {};
#pragma unroll
        for (int ks = 0; ks < 4; ks++) {
            const uint32_t ko = ks * 32u;
            uint32_t ah[4], al[4];
            ldmx4(ah, aQhi + ko);
            ldmx4(al, aQlo + ko);
#pragma unroll
            for (int jp = 0; jp < 4; jp++) {
                uint32_t bhv[4], blv[4];
                ldmx4(bhv, bKhi + jp * BSTEP + ko);
                ldmx4(blv, bKlo + jp * BSTEP + ko);
                mma_bf16(acc[2 * jp],     ah, bhv);
                mma_bf16(acc[2 * jp],     al, bhv);
                mma_bf16(acc[2 * jp],     ah, blv);
                mma_bf16(acc[2 * jp + 1], ah, bhv + 2);
                mma_bf16(acc[2 * jp + 1], al, bhv + 2);
                mma_bf16(acc[2 * jp + 1], ah, blv + 2);
            }
        }
        __syncthreads();

#pragma unroll
        for (int j = 0; j < 8; j++) {
            const int2 mj = *reinterpret_cast<const int2*>(
                mask + b * S + kt * 64 + j * 8 + 2 * tig);
            float v;
            v = acc[j][0] * 0.125f + og0; acc[j][0] = mj.x ? v : -1e9f;
            v = acc[j][1] * 0.125f + og0; acc[j][1] = mj.y ? v : -1e9f;
            v = acc[j][2] * 0.125f + og1; acc[j][2] = mj.x ? v : -1e9f;
            v = acc[j][3] * 0.125f + og1; acc[j][3] = mj.y ? v : -1e9f;
        }

        {
            float mt0 = -1e30f, mt1 = -1e30f;
#pragma unroll
            for (int j = 0; j < 8; j++) {
                mt0 = fmaxf(mt0, fmaxf(acc[j][0], acc[j][1]));
                mt1 = fmaxf(mt1, fmaxf(acc[j][2], acc[j][3]));
            }
            mt0 = fmaxf(mt0, __shfl_xor_sync(0xffffffffu, mt0, 1));
            mt0 = fmaxf(mt0, __shfl_xor_sync(0xffffffffu, mt0, 2));
            mt1 = fmaxf(mt1, __shfl_xor_sync(0xffffffffu, mt1, 1));
            mt1 = fmaxf(mt1, __shfl_xor_sync(0xffffffffu, mt1, 2));
            const float mn0 = fmaxf(rm0, mt0);
            const float mn1 = fmaxf(rm1, mt1);
            float s0 = 0.0f, s1 = 0.0f;
#pragma unroll
            for (int j = 0; j < 8; j++) {
                s0 += __expf(acc[j][0] - mn0) + __expf(acc[j][1] - mn0);
                s1 += __expf(acc[j][2] - mn1) + __expf(acc[j][3] - mn1);
            }
            s0 += __shfl_xor_sync(0xffffffffu, s0, 1);
            s0 += __shfl_xor_sync(0xffffffffu, s0, 2);
            s1 += __shfl_xor_sync(0xffffffffu, s1, 1);
            s1 += __shfl_xor_sync(0xffffffffu, s1, 2);
            rs0 = rs0 * __expf(rm0 - mn0) + s0; rm0 = mn0;
            rs1 = rs1 * __expf(rm1 - mn1) + s1; rm1 = mn1;
        }
    }

    if (tig == 0) {
        rowM[(size_t)bh * S + q0 + r0] = rm0;
        rowInv[(size_t)bh * S + q0 + r0] = 1.0f / rs0;
        rowM[(size_t)bh * S + q0 + r0 + 8] = rm1;
        rowInv[(size_t)bh * S + q0 + r0 + 8] = 1.0f / rs1;
    }
}

// ============================================================================
// av_fused: 256-thread CTA (8 warps), 128-row q-strip, FA2 register reuse.
// (R11 shape — measured best for av)
// ============================================================================
namespace {
constexpr int AF_QHI = 0;
constexpr int AF_QLO = 128 * KPS;
constexpr int AF_KHI = 2 * 128 * KPS;
constexpr int AF_KLO = AF_KHI + 64 * KPS;
constexpr int AF_VHI = AF_KLO + 64 * KPS;
constexpr int AF_VLO = AF_VHI + 64 * KPS;
constexpr int AF_RM  = AF_VLO + 64 * KPS;
constexpr int AF_RI  = AF_RM + 128;
constexpr int SMEM_AF = (AF_RI + 128) * 4;     // 74,752 bytes
}

__global__ void __launch_bounds__(256, 2) av_fused(
    const float* __restrict__ Q, const float* __restrict__ K,
    const float* __restrict__ V,
    const int* __restrict__ mask, const float* __restrict__ is_org,
    const float* __restrict__ Worg, const float* __restrict__ borg,
    const float* __restrict__ rowM, const float* __restrict__ rowInv,
    float* __restrict__ att, float* __restrict__ C)
{
    extern __shared__ uint32_t smu[];
    uint32_t* Qhi = smu + AF_QHI;
    uint32_t* Qlo = smu + AF_QLO;
    uint32_t* Khi = smu + AF_KHI;
    uint32_t* Klo = smu + AF_KLO;
    uint32_t* Vhi = smu + AF_VHI;
    uint32_t* Vlo = smu + AF_VLO;
    float*    Rm  = reinterpret_cast<float*>(smu + AF_RM);
    float*    Ri  = reinterpret_cast<float*>(smu + AF_RI);

    const int t = threadIdx.x, lane = t & 31, wid = t >> 5;   // wid 0..7
    const int g = lane >> 2, tig = lane & 3;
    const int bh = blockIdx.y, b = bh >> 3, h = bh & 7;
    const int q0 = blockIdx.x * 128;

    const float* Qg = Q + ((size_t)(b * S + q0)) * D + h * DK;
    const float* Kg = K + ((size_t)(b * S)) * D + h * DK;
    const float* Vg = V + ((size_t)(b * S)) * D + h * DK;

    if (t < 128) {
        Rm[t] = rowM[(size_t)bh * S + q0 + t];
        Ri[t] = rowInv[(size_t)bh * S + q0 + t];
    }
#pragma unroll
    for (int i = t; i < 2048; i += 256) {
        const int row = i >> 4, c4 = (i & 15) * 4, p = c4 >> 1;
        float4 qv = *reinterpret_cast<const float4*>(Qg + (size_t)row * D + c4);
        uint2 h2, l2;
        split_bf16x2(qv.x, qv.y, h2.x, l2.x);
        split_bf16x2(qv.z, qv.w, h2.y, l2.y);
        *reinterpret_cast<uint2*>(&Qhi[row * KPS + p]) = h2;
        *reinterpret_cast<uint2*>(&Qlo[row * KPS + p]) = l2;
    }

    const int am = lane >> 3, arm = lane & 7;
    uint32_t aQhi, aQlo;
    {
        const int row = wid * 16 + (am & 1) * 8 + arm;
        const uint32_t off = (uint32_t)(row * KPS + (am >> 1) * 4) * 4u;
        aQhi = smaddr(Qhi) + off;
        aQlo = smaddr(Qlo) + off;
    }
    uint32_t bKhi, bKlo, bVhi, bVlo;
    {
        const int brow = ((lane >> 4) & 1) * 8 + (lane & 7);
        const int bkp  = ((lane >> 3) & 1) * 4;
        const uint32_t off = (uint32_t)(brow * KPS + bkp) * 4u;
        bKhi = smaddr(Khi) + off; bKlo = smaddr(Klo) + off;
        bVhi = smaddr(Vhi) + off; bVlo = smaddr(Vlo) + off;
    }

    const float worg = __ldg(Worg + h), bog = __ldg(borg + h);
    const int r0 = wid * 16 + g;
    float og0 = __ldg(is_org + b * S + q0 + r0) * worg + bog;
    float og1 = __ldg(is_org + b * S + q0 + r0 + 8) * worg + bog;

    __syncthreads();
    const float M0 = Rm[r0], I0 = Ri[r0];
    const float M1 = Rm[r0 + 8], I1 = Ri[r0 + 8];

    float accAV[8][4] = {};

    for (int kt = 0; kt < 32; kt++) {
#pragma unroll
        for (int i = t; i < 1024; i += 256) {
            const int row = i >> 4, c4 = (i & 15) * 4, p = c4 >> 1;
            float4 kv = *reinterpret_cast<const float4*>(
                Kg + (size_t)(kt * 64 + row) * D + c4);
            uint2 h2, l2;
            split_bf16x2(kv.x, kv.y, h2.x, l2.x);
            split_bf16x2(kv.z, kv.w, h2.y, l2.y);
            *reinterpret_cast<uint2*>(&Khi[row * KPS + p]) = h2;
            *reinterpret_cast<uint2*>(&Klo[row * KPS + p]) = l2;
        }
#pragma unroll
        for (int i = t; i < 512; i += 256) {
            const int dg = i & 15, kp = i >> 4;
            const float* vp = Vg + (size_t)(kt * 64 + 2 * kp) * D + dg * 4;
            float4 va = *reinterpret_cast<const float4*>(vp);
            float4 vb = *reinterpret_cast<const float4*>(vp + D);
            uint32_t hi, lo;
            split_bf16x2(va.x, vb.x, hi, lo);
            Vhi[(dg * 4 + 0) * KPS + kp] = hi; Vlo[(dg * 4 + 0) * KPS + kp] = lo;
            split_bf16x2(va.y, vb.y, hi, lo);
            Vhi[(dg * 4 + 1) * KPS + kp] = hi; Vlo[(dg * 4 + 1) * KPS + kp] = lo;
            split_bf16x2(va.z, vb.z, hi, lo);
            Vhi[(dg * 4 + 2) * KPS + kp] = hi; Vlo[(dg * 4 + 2) * KPS + kp] = lo;
            split_bf16x2(va.w, vb.w, hi, lo);
            Vhi[(dg * 4 + 3) * KPS + kp] = hi; Vlo[(dg * 4 + 3) * KPS + kp] = lo;
        }
        __syncthreads();

        // QK
        float acc[8][4] = {};
#pragma unroll
        for (int ks = 0; ks < 4; ks++) {
            const uint32_t ko = ks * 32u;
            uint32_t ah[4], al[4];
            ldmx4(ah, aQhi + ko);
            ldmx4(al, aQlo + ko);
#pragma unroll
            for (int jp = 0; jp < 4; jp++) {
                uint32_t bhv[4], blv[4];
                ldmx4(bhv, bKhi + jp * BSTEP + ko);
                ldmx4(blv, bKlo + jp * BSTEP + ko);
                mma_bf16(acc[2 * jp],     ah, bhv);
                mma_bf16(acc[2 * jp],     al, bhv);
                mma_bf16(acc[2 * jp],     ah, blv);
                mma_bf16(acc[2 * jp + 1], ah, bhv + 2);
                mma_bf16(acc[2 * jp + 1], al, bhv + 2);
                mma_bf16(acc[2 * jp + 1], ah, blv + 2);
            }
        }

        // Softmax epilogue: p = exp(x - M) * Inv; write p to att; keep in acc
        float* arow0 = &att[((size_t)bh * S + q0 + r0) * S + kt * 64 + 2 * tig];
        float* arow1 = arow0 + 8 * S;
#pragma unroll
        for (int j = 0; j < 8; j++) {
            const int2 mj = *reinterpret_cast<const int2*>(
                mask + b * S + kt * 64 + j * 8 + 2 * tig);
            float x0 = acc[j][0] * 0.125f + og0;
            float x1 = acc[j][1] * 0.125f + og0;
            float x2 = acc[j][2] * 0.125f + og1;
            float x3 = acc[j][3] * 0.125f + og1;
            x0 = mj.x ? x0 : -1e9f;
            x1 = mj.y ? x1 : -1e9f;
            x2 = mj.x ? x2 : -1e9f;
            x3 = mj.y ? x3 : -1e9f;
            const float p0 = __expf(x0 - M0) * I0;
            const float p1 = __expf(x1 - M0) * I0;
            const float p2 = __expf(x2 - M1) * I1;
            const float p3 = __expf(x3 - M1) * I1;
            float2 o;
            o.x = p0; o.y = p1;
            *reinterpret_cast<float2*>(arow0 + j * 8) = o;
            o.x = p2; o.y = p3;
            *reinterpret_cast<float2*>(arow1 + j * 8) = o;
            acc[j][0] = p0; acc[j][1] = p1; acc[j][2] = p2; acc[j][3] = p3;
        }

        // PV: A-frags packed directly from acc
#pragma unroll
        for (int jj = 0; jj < 4; jj++) {
            uint32_t ph[4], pl[4];
            split_bf16x2(acc[2 * jj][0],     acc[2 * jj][1],     ph[0], pl[0]);
            split_bf16x2(acc[2 * jj][2],     acc[2 * jj][3],     ph[1], pl[1]);
            split_bf16x2(acc[2 * jj + 1][0], acc[2 * jj + 1][1], ph[2], pl[2]);
            split_bf16x2(acc[2 * jj + 1][2], acc[2 * jj + 1][3], ph[3], pl[3]);
            const uint32_t ko = jj * 32u;
#pragma unroll
            for (int dp = 0; dp < 4; dp++) {
                uint32_t vh[4], vl[4];
                ldmx4(vh, bVhi + dp * BSTEP + ko);
                ldmx4(vl, bVlo + dp * BSTEP + ko);
                mma_bf16(accAV[2 * dp],     ph, vh);
                mma_bf16(accAV[2 * dp],     pl, vh);
                mma_bf16(accAV[2 * dp],     ph, vl);
                mma_bf16(accAV[2 * dp + 1], ph, vh + 2);
                mma_bf16(accAV[2 * dp + 1], pl, vh + 2);
                mma_bf16(accAV[2 * dp + 1], ph, vl + 2);
            }
        }
        __syncthreads();
    }

    // Store context C
#pragma unroll
    for (int dj = 0; dj < 8; dj++) {
        const int col = h * DK + dj * 8 + 2 * tig;
        float2 o;
        o.x = accAV[dj][0]; o.y = accAV[dj][1];
        *reinterpret_cast<float2*>(&C[(size_t)(b * S + q0 + r0) * D + col]) = o;
        o.x = accAV[dj][2]; o.y = accAV[dj][3];
        *reinterpret_cast<float2*>(&C[(size_t)(b * S + q0 + r0 + 8) * D + col]) = o;
    }
}

// ---------------------------------------------------------------------------
extern "C" void kernel_launch(void* const* d_in, const int* in_sizes, int n_in,
                              void* d_out, int out_size)
{
    const float* query = (const float*)d_in[0];
    const float* key   = (const float*)d_in[1];
    const float* value = (const float*)d_in[2];
    const int*   mask  = (const int*)d_in[3];
    const float* isog  = (const float*)d_in[4];
    const float* Wq    = (const float*)d_in[5];
    const float* bq    = (const float*)d_in[6];
    const float* Wk    = (const float*)d_in[7];
    const float* bk    = (const float*)d_in[8];
    const float* Wv    = (const float*)d_in[9];
    const float* bv    = (const float*)d_in[10];
    const float* Wo    = (const float*)d_in[11];
    const float* bo    = (const float*)d_in[12];
    const float* Worg  = (const float*)d_in[13];
    const float* borg  = (const float*)d_in[14];

    float* out = (float*)d_out;

    float *qbuf, *kbuf, *vbuf, *cbuf, *rowM, *rowInv;
    cudaGetSymbolAddress((void**)&qbuf, g_Q);
    cudaGetSymbolAddress((void**)&kbuf, g_K);
    cudaGetSymbolAddress((void**)&vbuf, g_V);
    cudaGetSymbolAddress((void**)&cbuf, g_C);
    cudaGetSymbolAddress((void**)&rowM, g_rowM);
    cudaGetSymbolAddress((void**)&rowInv, g_rowInv);

    const long long OUT_MAIN = (long long)B * S * D;
    const long long ATT_SZ   = (long long)B * H * S * S;
    float* att;
    if ((long long)out_size >= OUT_MAIN + ATT_SZ) {
        att = out + OUT_MAIN;
    } else {
        cudaGetSymbolAddress((void**)&att, g_att);
    }

    static bool attr_done = false;
    if (!attr_done) {
        cudaFuncSetAttribute(gemm_mma,  cudaFuncAttributeMaxDynamicSharedMemorySize, SMEM_GEMM);
        cudaFuncSetAttribute(stats_mma, cudaFuncAttributeMaxDynamicSharedMemorySize, SMEM_STATS);
        cudaFuncSetAttribute(av_fused,  cudaFuncAttributeMaxDynamicSharedMemorySize, SMEM_AF);
        attr_done = true;
    }

    dim3 gg(4, 64);
    gemm_mma<<<gg, 256, SMEM_GEMM>>>(query, Wq, bq, qbuf);
    gemm_mma<<<gg, 256, SMEM_GEMM>>>(key,   Wk, bk, kbuf);
    gemm_mma<<<gg, 256, SMEM_GEMM>>>(value, Wv, bv, vbuf);

    dim3 gs(S / 64, B * H);
    stats_mma<<<gs, 128, SMEM_STATS>>>(qbuf, kbuf, mask, isog, Worg, borg, rowM, rowInv);

    dim3 ga(S / 128, B * H);
    av_fused<<<ga, 256, SMEM_AF>>>(qbuf, kbuf, vbuf, mask, isog, Worg, borg,
                                   rowM, rowInv, att, cbuf);

    gemm_mma<<<gg, 256, SMEM_GEMM>>>(cbuf, Wo, bo, out);
}